// round 13
// baseline (speedup 1.0000x reference)
#include <cuda_runtime.h>
#include <cuda_fp16.h>
#include <math.h>
#include <stdint.h>

#define BB   2
#define SS   1024
#define DD   1024
#define HH   16
#define HDD  1024
#define FF   4096
#define LL   4
#define MR   (BB*SS)
#define NQKV 3072

// -------------------- scratch --------------------
__device__ float g_x  [MR * DD];
__device__ float g_tmp[MR * DD];
__device__ float g_maskf[MR];
__device__ __half g_xh[MR * DD];
__device__ __half g_qkv[(size_t)MR * NQKV];
__device__ __half g_ch[MR * HDD];
__device__ __half g_fh[(size_t)MR * FF];
__device__ float g_bqkv[LL * NQKV];

#define SZ_P ((size_t)HDD * DD)
#define SZ_F ((size_t)DD * FF)
#define WQKV_OFF ((size_t)0)
#define WOT_OFF  ((size_t)LL * 3 * SZ_P)
#define W1T_OFF  (WOT_OFF + (size_t)LL * SZ_P)
#define W2T_OFF  (W1T_OFF + (size_t)LL * SZ_F)
#define WT_TOTAL (W2T_OFF + (size_t)LL * SZ_F)
__device__ __half g_wh[WT_TOTAL];

// ==================== helpers ====================
__device__ __forceinline__ uint32_t smem_to_u32(const void* p) {
    uint32_t a;
    asm("{ .reg .u64 t; cvta.to.shared.u64 t, %1; cvt.u32.u64 %0, t; }" : "=r"(a) : "l"(p));
    return a;
}
#define CP_ASYNC16(dst, src) \
    asm volatile("cp.async.cg.shared.global [%0], [%1], 16;" \
        :: "r"((uint32_t)(dst)), "l"(__cvta_generic_to_global(src)) : "memory")
#define CP_COMMIT() asm volatile("cp.async.commit_group;" ::: "memory")
#define CP_WAITG(n) asm volatile("cp.async.wait_group %0;" :: "n"(n) : "memory")
#define LDM_X4(r0, r1, r2, r3, addr) \
    asm volatile("ldmatrix.sync.aligned.m8n8.x4.shared.b16 {%0,%1,%2,%3}, [%4];" \
        : "=r"(r0), "=r"(r1), "=r"(r2), "=r"(r3) : "r"(addr))
#define LDM_X4_T(r0, r1, r2, r3, addr) \
    asm volatile("ldmatrix.sync.aligned.m8n8.x4.trans.shared.b16 {%0,%1,%2,%3}, [%4];" \
        : "=r"(r0), "=r"(r1), "=r"(r2), "=r"(r3) : "r"(addr))
#define MMA_F16(acc, a, b0, b1) \
    asm volatile("mma.sync.aligned.m16n8k16.row.col.f32.f16.f16.f32 " \
        "{%0,%1,%2,%3},{%4,%5,%6,%7},{%8,%9},{%0,%1,%2,%3};" \
        : "+f"((acc)[0]), "+f"((acc)[1]), "+f"((acc)[2]), "+f"((acc)[3]) \
        : "r"((a)[0]), "r"((a)[1]), "r"((a)[2]), "r"((a)[3]), "r"(b0), "r"(b1))

__device__ __forceinline__ uint32_t hpk2(float a, float b) {
    __half2 t = __floats2half2_rn(a, b);
    return *reinterpret_cast<uint32_t*>(&t);
}
__device__ __forceinline__ float gelu_f(float v) {
    float x = v * 0.70710678118654752f;
    float ax = fabsf(x);
    float t = __fdividef(1.0f, fmaf(0.3275911f, ax, 1.0f));
    float p = t * fmaf(t, fmaf(t, fmaf(t, fmaf(t, 1.061405429f, -1.453152027f),
                               1.421413741f), -0.284496736f), 0.254829592f);
    float erfv = 1.0f - p * __expf(-ax * ax);
    erfv = copysignf(erfv, x);
    return 0.5f * v * (1.0f + erfv);
}

// ==================== batched weight transpose ====================
__device__ __forceinline__ void tsplit_body(
    const float* __restrict__ W, __half* __restrict__ th, int K, int N)
{
    __shared__ float ts[64][65];
    const int n0 = blockIdx.x * 64, k0 = blockIdx.y * 64;
    const int tid = threadIdx.x;
    #pragma unroll
    for (int i = 0; i < 4; i++) {
        int e = tid + i * 256;
        int r = e >> 4, c4 = (e & 15) * 4;
        float4 v = *(const float4*)&W[(size_t)(k0 + r) * N + n0 + c4];
        ts[r][c4]     = v.x; ts[r][c4 + 1] = v.y;
        ts[r][c4 + 2] = v.z; ts[r][c4 + 3] = v.w;
    }
    __syncthreads();
    const int w = tid >> 5, lane = tid & 31;
    #pragma unroll
    for (int rr = 0; rr < 8; rr++) {
        int n = w * 8 + rr;
        float a = ts[lane * 2][n], b = ts[lane * 2 + 1][n];
        size_t o = (size_t)(n0 + n) * K + k0 + lane * 2;
        *(uint32_t*)&th[o] = hpk2(a, b);
    }
}

__global__ __launch_bounds__(256) void tsplit_qkv(
    const float* __restrict__ Wq, const float* __restrict__ Wk,
    const float* __restrict__ Wv, __half* __restrict__ th)
{
    int z = blockIdx.z;
    int l = z / 3, j = z - l * 3;
    const float* W = ((j == 0) ? Wq : (j == 1) ? Wk : Wv) + (size_t)l * SZ_P;
    __half* dst = th + ((size_t)l * 3 + j) * SZ_P;
    tsplit_body(W, dst, DD, HDD);
}

__global__ __launch_bounds__(256) void tsplit_b(
    const float* __restrict__ W, __half* __restrict__ th, int K, int N)
{
    size_t off = (size_t)blockIdx.z * K * N;
    tsplit_body(W + off, th + off, K, N);
}

__global__ void biascat_kernel(const float* __restrict__ bq, const float* __restrict__ bk,
                               const float* __restrict__ bv, float* __restrict__ o)
{
    int i = blockIdx.x * 256 + threadIdx.x;
    int l = i / NQKV, r = i % NQKV;
    int seg = r >> 10, n = r & 1023;
    const float* s = (seg == 0) ? bq : (seg == 1) ? bk : bv;
    o[i] = s[l * 1024 + n];
}

__global__ void mask_kernel(const int* __restrict__ tok, float* __restrict__ m)
{
    int i = blockIdx.x * 256 + threadIdx.x;
    m[i] = (tok[i] == 0) ? -1e9f : 0.f;
}

// ==================== fp16 HMMA GEMM, single-barrier 4-slot pipeline ====================
#define KC 32
#define ARR_B 10240

template<int MT>
__global__ __launch_bounds__(256, 2) void gemm_mma(
    const __half* __restrict__ A, const __half* __restrict__ B,
    const float* __restrict__ bias, float* __restrict__ C,
    __half* __restrict__ Ch, int K, int N, int act)
{
    constexpr uint32_t ARR_A = (uint32_t)MT * 80;
    constexpr uint32_t STGB  = ARR_A + ARR_B;
    constexpr int AITER = MT / 64;
    constexpr int NFRAG = (MT == 128) ? 8 : 4;
    constexpr int NB    = NFRAG / 2;
    constexpr int WNW   = (MT == 128) ? 64 : 32;

    extern __shared__ __align__(128) char smem_raw[];
    const uint32_t sbase = smem_to_u32(smem_raw);

    const int tid  = threadIdx.x;
    const int lane = tid & 31;
    const int wid  = tid >> 5;
    const int wm   = (MT == 128) ? (wid & 3) : (wid & 1);
    const int wn   = (MT == 128) ? (wid >> 2) : (wid >> 1);
    const int m0 = blockIdx.y * MT, n0 = blockIdx.x * 128;

    float acc[2][NFRAG][4];
    #pragma unroll
    for (int i = 0; i < 2; i++)
        #pragma unroll
        for (int j = 0; j < NFRAG; j++)
            #pragma unroll
            for (int q2 = 0; q2 < 4; q2++) acc[i][j][q2] = 0.f;

    const int nc = K >> 5;

    #define FILL_STAGE(stg, kk) do { \
        const uint32_t so_ = sbase + (uint32_t)(stg) * STGB; \
        _Pragma("unroll") \
        for (int i_ = 0; i_ < AITER + 2; i_++) { \
            const int isA_ = (i_ < AITER); \
            int rem_ = (isA_ ? i_ : (i_ - AITER)) * 256 + tid; \
            int row_ = rem_ >> 2, seg_ = rem_ & 3; \
            const __half* p_ = isA_ ? A : B; \
            int rb_ = isA_ ? m0 : n0; \
            uint32_t dst_ = so_ + (isA_ ? 0u : ARR_A) + row_ * 80 + seg_ * 16; \
            CP_ASYNC16(dst_, p_ + (size_t)(rb_ + row_) * K + (kk) + seg_ * 8); \
        } \
        CP_COMMIT(); \
    } while (0)

    FILL_STAGE(0, 0);
    FILL_STAGE(1, KC);

    const uint32_t lrow  = lane & 15;
    const uint32_t khalf = lane >> 4;
    const uint32_t a_row_off = (wm * 32 + lrow) * 80;
    const uint32_t b_row_off = (wn * WNW + lrow) * 80;

    for (int c = 0; c < nc; c++) {
        if (c + 2 < nc) { FILL_STAGE((c + 2) & 3, (c + 2) * KC); CP_WAITG(2); }
        else if (c + 1 < nc) CP_WAITG(1);
        else CP_WAITG(0);
        __syncthreads();

        const uint32_t so = sbase + (uint32_t)(c & 3) * STGB;
        const uint32_t sA = so, sB = so + ARR_A;

        #pragma unroll
        for (int ks = 0; ks < 2; ks++) {
            const uint32_t kofs = (ks * 16 + khalf * 8) * 2;
            uint32_t af[2][4];
            #pragma unroll
            for (int mb = 0; mb < 2; mb++) {
                uint32_t ad = a_row_off + mb * 16 * 80 + kofs;
                LDM_X4(af[mb][0], af[mb][1], af[mb][2], af[mb][3], sA + ad);
            }
            #pragma unroll
            for (int nb = 0; nb < NB; nb++) {
                uint32_t bd = b_row_off + nb * 16 * 80 + kofs;
                uint32_t bf_[4];
                LDM_X4(bf_[0], bf_[1], bf_[2], bf_[3], sB + bd);
                #pragma unroll
                for (int mb = 0; mb < 2; mb++) {
                    MMA_F16(acc[mb][nb * 2],     af[mb], bf_[0], bf_[2]);
                    MMA_F16(acc[mb][nb * 2 + 1], af[mb], bf_[1], bf_[3]);
                }
            }
        }
    }
    #undef FILL_STAGE

    const int mrow = m0 + wm * 32 + (lane >> 2);
    const int ncol0 = n0 + wn * WNW + (lane & 3) * 2;
    #pragma unroll
    for (int mb = 0; mb < 2; mb++) {
        #pragma unroll
        for (int nf = 0; nf < NFRAG; nf++) {
            int n = ncol0 + nf * 8;
            float b0v = bias ? bias[n]     : 0.f;
            float b1v = bias ? bias[n + 1] : 0.f;
            float v0 = acc[mb][nf][0] + b0v;
            float v1 = acc[mb][nf][1] + b1v;
            float v2 = acc[mb][nf][2] + b0v;
            float v3 = acc[mb][nf][3] + b1v;
            if (act) { v0 = gelu_f(v0); v1 = gelu_f(v1); v2 = gelu_f(v2); v3 = gelu_f(v3); }
            int m = mrow + mb * 16;
            if (C) {
                *(float2*)(C + (size_t)m * N + n)       = make_float2(v0, v1);
                *(float2*)(C + (size_t)(m + 8) * N + n) = make_float2(v2, v3);
            }
            if (Ch) {
                *(uint32_t*)(Ch + (size_t)m * N + n)       = hpk2(v0, v1);
                *(uint32_t*)(Ch + (size_t)(m + 8) * N + n) = hpk2(v2, v3);
            }
        }
    }
}

// ==================== flash attention (fp16, 64-key tiles, 4-stage, race-free) ====================
// 4 slots + prefetch distance 2: FILL(kt+2) targets slot (kt-2)&3, whose consumers
// all passed the __syncthreads() of iteration kt-1 before any warp issues this fill.
#define FA_Q     0
#define FA_STG0  18432
#define FA_K     0
#define FA_V     9216
#define FA_MSK   18432
#define FA_STGSZ 18688
#define FA_SMEM  (18432 + 4 * 18688)   // 93184; x2 CTAs = 182KB < 228KB/SM

__global__ __launch_bounds__(256, 2) void flash_attn(
    const __half* __restrict__ qkv, const float* __restrict__ maskg,
    __half* __restrict__ ch)
{
    extern __shared__ __align__(128) char smem_raw[];
    const uint32_t base = smem_to_u32(smem_raw);
    const uint32_t sQ = base + FA_Q;

    const int tid = threadIdx.x, lane = tid & 31, wid = tid >> 5;
    const int q0 = blockIdx.x * 128;
    const int z = blockIdx.y, b = z >> 4, h = z & 15;
    const uint32_t lrow = lane & 15, khalf = lane >> 4;
    const int cpos = (lane & 3) * 2;
    const int colQ = h * 64, colK = 1024 + h * 64, colV = 2048 + h * 64;

    #pragma unroll
    for (int i = 0; i < 2; i++) {
        int idx = tid + i * 256;
        int row = idx >> 2, seg2 = (idx & 3) * 2;
        size_t src = (size_t)(b * SS + q0 + row) * NQKV + colQ + seg2 * 8;
        CP_ASYNC16(sQ + row * 144 + seg2 * 16, qkv + src);
        CP_ASYNC16(sQ + row * 144 + seg2 * 16 + 16, qkv + src + 8);
    }
    CP_COMMIT();

    #define FA_FILL(kt_) do { \
        const int stg_ = (kt_) & 3; \
        const uint32_t sb_ = base + FA_STG0 + stg_ * FA_STGSZ; \
        const int k0_ = (kt_) * 64; \
        { int row_ = tid >> 2, s2_ = tid & 3; \
          size_t srck_ = (size_t)(b * SS + k0_ + row_) * NQKV + colK + s2_ * 16; \
          uint32_t dstk_ = sb_ + FA_K + row_ * 144 + s2_ * 32; \
          CP_ASYNC16(dstk_, qkv + srck_); \
          CP_ASYNC16(dstk_ + 16, qkv + srck_ + 8); \
          size_t srcv_ = (size_t)(b * SS + k0_ + row_) * NQKV + colV + s2_ * 16; \
          uint32_t dstv_ = sb_ + FA_V + row_ * 144 + s2_ * 32; \
          CP_ASYNC16(dstv_, qkv + srcv_); \
          CP_ASYNC16(dstv_ + 16, qkv + srcv_ + 8); } \
        if (tid < 16) \
            CP_ASYNC16(sb_ + FA_MSK + tid * 16, maskg + b * SS + k0_ + tid * 4); \
        CP_COMMIT(); \
    } while (0)

    FA_FILL(0);
    FA_FILL(1);

    float m0 = -3.0e38f, m1 = -3.0e38f, l0 = 0.f, l1 = 0.f;
    float O[8][4];
    #pragma unroll
    for (int i = 0; i < 8; i++)
        #pragma unroll
        for (int j = 0; j < 4; j++) O[i][j] = 0.f;

    uint32_t qf[4][4];

    for (int kt = 0; kt < 16; kt++) {
        if (kt + 2 < 16) { FA_FILL(kt + 2); CP_WAITG(2); }
        else if (kt + 1 < 16) CP_WAITG(1);
        else CP_WAITG(0);
        __syncthreads();

        const uint32_t sb = base + FA_STG0 + (uint32_t)(kt & 3) * FA_STGSZ;
        const uint32_t sK = sb + FA_K, sV = sb + FA_V;
        const float* maskf = (const float*)(smem_raw + FA_STG0 + (kt & 3) * FA_STGSZ + FA_MSK);

        if (kt == 0) {
            #pragma unroll
            for (int ks = 0; ks < 4; ks++) {
                uint32_t ad = (wid * 16 + lrow) * 144 + (ks * 16 + khalf * 8) * 2;
                LDM_X4(qf[ks][0], qf[ks][1], qf[ks][2], qf[ks][3], sQ + ad);
            }
        }

        float Sv[8][4];
        #pragma unroll
        for (int i = 0; i < 8; i++)
            #pragma unroll
            for (int j = 0; j < 4; j++) Sv[i][j] = 0.f;

        #pragma unroll
        for (int ks = 0; ks < 4; ks++) {
            #pragma unroll
            for (int ng = 0; ng < 4; ng++) {
                uint32_t bd = (ng * 16 + lrow) * 144 + (ks * 16 + khalf * 8) * 2;
                uint32_t bh_[4];
                LDM_X4(bh_[0], bh_[1], bh_[2], bh_[3], sK + bd);
                MMA_F16(Sv[2 * ng],     qf[ks], bh_[0], bh_[2]);
                MMA_F16(Sv[2 * ng + 1], qf[ks], bh_[1], bh_[3]);
            }
        }

        float mt0 = -3.0e38f, mt1 = -3.0e38f;
        #pragma unroll
        for (int nb = 0; nb < 8; nb++) {
            float mk0 = maskf[nb * 8 + cpos], mk1 = maskf[nb * 8 + cpos + 1];
            Sv[nb][0] = Sv[nb][0] * 0.125f + mk0;
            Sv[nb][1] = Sv[nb][1] * 0.125f + mk1;
            Sv[nb][2] = Sv[nb][2] * 0.125f + mk0;
            Sv[nb][3] = Sv[nb][3] * 0.125f + mk1;
            mt0 = fmaxf(mt0, fmaxf(Sv[nb][0], Sv[nb][1]));
            mt1 = fmaxf(mt1, fmaxf(Sv[nb][2], Sv[nb][3]));
        }
        mt0 = fmaxf(mt0, __shfl_xor_sync(0xffffffffu, mt0, 1));
        mt0 = fmaxf(mt0, __shfl_xor_sync(0xffffffffu, mt0, 2));
        mt1 = fmaxf(mt1, __shfl_xor_sync(0xffffffffu, mt1, 1));
        mt1 = fmaxf(mt1, __shfl_xor_sync(0xffffffffu, mt1, 2));

        float mn0 = fmaxf(m0, mt0), mn1 = fmaxf(m1, mt1);
        float al0 = __expf(m0 - mn0), al1 = __expf(m1 - mn1);
        float su0 = 0.f, su1 = 0.f;
        #pragma unroll
        for (int nb = 0; nb < 8; nb++) {
            Sv[nb][0] = __expf(Sv[nb][0] - mn0);
            Sv[nb][1] = __expf(Sv[nb][1] - mn0);
            Sv[nb][2] = __expf(Sv[nb][2] - mn1);
            Sv[nb][3] = __expf(Sv[nb][3] - mn1);
            su0 += Sv[nb][0] + Sv[nb][1];
            su1 += Sv[nb][2] + Sv[nb][3];
        }
        su0 += __shfl_xor_sync(0xffffffffu, su0, 1);
        su0 += __shfl_xor_sync(0xffffffffu, su0, 2);
        su1 += __shfl_xor_sync(0xffffffffu, su1, 1);
        su1 += __shfl_xor_sync(0xffffffffu, su1, 2);

        l0 = l0 * al0 + su0;
        l1 = l1 * al1 + su1;
        m0 = mn0; m1 = mn1;
        #pragma unroll
        for (int nf = 0; nf < 8; nf++) {
            O[nf][0] *= al0; O[nf][1] *= al0;
            O[nf][2] *= al1; O[nf][3] *= al1;
        }

        #pragma unroll
        for (int j = 0; j < 4; j++) {
            uint32_t pa[4];
            pa[0] = hpk2(Sv[2*j][0],   Sv[2*j][1]);
            pa[1] = hpk2(Sv[2*j][2],   Sv[2*j][3]);
            pa[2] = hpk2(Sv[2*j+1][0], Sv[2*j+1][1]);
            pa[3] = hpk2(Sv[2*j+1][2], Sv[2*j+1][3]);
            #pragma unroll
            for (int ng = 0; ng < 4; ng++) {
                uint32_t bd = sV + (j * 16 + lrow) * 144 + (ng * 16 + khalf * 8) * 2;
                uint32_t v0, v1, v2, v3;
                LDM_X4_T(v0, v1, v2, v3, bd);
                MMA_F16(O[2 * ng],     pa, v0, v1);
                MMA_F16(O[2 * ng + 1], pa, v2, v3);
            }
        }
    }
    #undef FA_FILL

    float i0 = 1.f / l0, i1 = 1.f / l1;
    const int rgl = b * SS + q0 + wid * 16 + (lane >> 2);
    #pragma unroll
    for (int nf = 0; nf < 8; nf++) {
        int col = h * 64 + nf * 8 + cpos;
        size_t o0 = (size_t)rgl * HDD + col;
        size_t o1 = (size_t)(rgl + 8) * HDD + col;
        *(uint32_t*)(ch + o0) = hpk2(O[nf][0] * i0, O[nf][1] * i0);
        *(uint32_t*)(ch + o1) = hpk2(O[nf][2] * i1, O[nf][3] * i1);
    }
}

// ==================== embed + add_ln ====================
__global__ __launch_bounds__(256) void embed_kernel(
    const int* __restrict__ tok, const float* __restrict__ emb,
    float* __restrict__ x, __half* __restrict__ xh)
{
    int row = blockIdx.x;
    int s = row % SS;
    int t = tok[row];
    const float* e = emb + (size_t)t * DD;
    for (int d = threadIdx.x; d < DD; d += 256) {
        int i = d >> 1;
        float freq = expf(-((float)(2 * i) / (float)DD) * 9.210340371976184f);
        float a = (float)s * freq;
        float pe = (d & 1) ? cosf(a) : sinf(a);
        float v = e[d] + pe;
        size_t o = (size_t)row * DD + d;
        x[o] = v;
        xh[o] = __float2half_rn(v);
    }
}

__device__ __forceinline__ float block_sum(float v, float* sh) {
    __syncthreads();
    #pragma unroll
    for (int o = 16; o > 0; o >>= 1) v += __shfl_xor_sync(0xffffffffu, v, o);
    int w = threadIdx.x >> 5;
    if ((threadIdx.x & 31) == 0) sh[w] = v;
    __syncthreads();
    float t = (threadIdx.x < 8) ? sh[threadIdx.x] : 0.0f;
    #pragma unroll
    for (int o = 4; o > 0; o >>= 1) t += __shfl_xor_sync(0xffffffffu, t, o);
    if (threadIdx.x == 0) sh[0] = t;
    __syncthreads();
    return sh[0];
}

__global__ __launch_bounds__(256) void add_ln(
    const float* __restrict__ xin, const float* __restrict__ delta,
    const float* __restrict__ g, const float* __restrict__ bta,
    float* __restrict__ out, __half* __restrict__ oh)
{
    size_t row = blockIdx.x;
    const float* xr = xin   + row * DD;
    const float* dr = delta + row * DD;
    int tid = threadIdx.x;
    __shared__ float red[8];

    float v[4];
    float s = 0.f;
    #pragma unroll
    for (int j = 0; j < 4; j++) {
        int c = tid + j * 256;
        v[j] = xr[c] + dr[c];
        s += v[j];
    }
    s = block_sum(s, red);
    float mu = s * (1.0f / 1024.0f);
    float var = 0.f;
    #pragma unroll
    for (int j = 0; j < 4; j++) { float t = v[j] - mu; var += t * t; }
    var = block_sum(var, red) * (1.0f / 1024.0f);
    float inv = rsqrtf(var + 1e-5f);
    #pragma unroll
    for (int j = 0; j < 4; j++) {
        int c = tid + j * 256;
        float o = (v[j] - mu) * inv * g[c] + bta[c];
        size_t idx = row * DD + c;
        out[idx] = o;
        if (oh) oh[idx] = __float2half_rn(o);
    }
}

// ==================== host orchestration ====================
extern "C" void kernel_launch(void* const* d_in, const int* in_sizes, int n_in,
                              void* d_out, int out_size)
{
    (void)in_sizes; (void)n_in; (void)out_size;
    const int*   tok  = (const int*)  d_in[0];
    const float* emb  = (const float*)d_in[1];
    const float* Wq   = (const float*)d_in[2];
    const float* bq   = (const float*)d_in[3];
    const float* Wk   = (const float*)d_in[4];
    const float* bk   = (const float*)d_in[5];
    const float* Wv   = (const float*)d_in[6];
    const float* bv   = (const float*)d_in[7];
    const float* Wo   = (const float*)d_in[8];
    const float* bo   = (const float*)d_in[9];
    const float* ln1g = (const float*)d_in[10];
    const float* ln1b = (const float*)d_in[11];
    const float* W1   = (const float*)d_in[12];
    const float* W2   = (const float*)d_in[13];
    const float* ln2g = (const float*)d_in[14];
    const float* ln2b = (const float*)d_in[15];
    float* out = (float*)d_out;

    float *x, *tmp, *bqkv, *maskg;
    __half *xh, *qkv, *ch, *fh, *wh;
    cudaGetSymbolAddress((void**)&x,     g_x);
    cudaGetSymbolAddress((void**)&tmp,   g_tmp);
    cudaGetSymbolAddress((void**)&maskg, g_maskf);
    cudaGetSymbolAddress((void**)&xh,    g_xh);
    cudaGetSymbolAddress((void**)&qkv,   g_qkv);
    cudaGetSymbolAddress((void**)&ch,    g_ch);
    cudaGetSymbolAddress((void**)&fh,    g_fh);
    cudaGetSymbolAddress((void**)&wh,    g_wh);
    cudaGetSymbolAddress((void**)&bqkv,  g_bqkv);

    const int GSM128 = 4 * (128 * 80 + ARR_B);   // 81920
    const int GSM64  = 4 * (64 * 80 + ARR_B);    // 61440

    static int attr_done = 0;
    static cudaStream_t s2;
    static cudaEvent_t evFork, evJoin;
    if (!attr_done) {
        cudaFuncSetAttribute(gemm_mma<128>, cudaFuncAttributeMaxDynamicSharedMemorySize, GSM128);
        cudaFuncSetAttribute(gemm_mma<64>,  cudaFuncAttributeMaxDynamicSharedMemorySize, GSM64);
        cudaFuncSetAttribute(flash_attn, cudaFuncAttributeMaxDynamicSharedMemorySize, FA_SMEM);
        cudaStreamCreateWithFlags(&s2, cudaStreamNonBlocking);
        cudaEventCreateWithFlags(&evFork, cudaEventDisableTiming);
        cudaEventCreateWithFlags(&evJoin, cudaEventDisableTiming);
        attr_done = 1;
    }

    // prep on main stream (needed before first QKV gemm)
    mask_kernel<<<MR / 256, 256>>>(tok, maskg);
    biascat_kernel<<<LL * NQKV / 256, 256>>>(bq, bk, bv, bqkv);
    embed_kernel<<<MR, 256>>>(tok, emb, x, xh);
    tsplit_qkv<<<dim3(HDD/64, DD/64, LL*3), 256>>>(Wq, Wk, Wv, wh + WQKV_OFF);

    // fork: Wo/W1/W2 transposes overlap with layer-0 QKV gemm + flash
    cudaEventRecord(evFork, 0);
    cudaStreamWaitEvent(s2, evFork, 0);
    tsplit_b<<<dim3(DD/64, HDD/64, LL), 256, 0, s2>>>(Wo, wh + WOT_OFF, HDD, DD);
    tsplit_b<<<dim3(FF/64, DD/64, LL), 256, 0, s2>>>(W1, wh + W1T_OFF, DD, FF);
    tsplit_b<<<dim3(DD/64, FF/64, LL), 256, 0, s2>>>(W2, wh + W2T_OFF, FF, DD);
    cudaEventRecord(evJoin, s2);

    dim3 gQKV(NQKV/128, MR/128);   // MT=128
    dim3 gWo(DD/128, MR/64);       // MT=64
    dim3 gF1(FF/128, MR/128);      // MT=128
    dim3 gF2(DD/128, MR/64);       // MT=64
    dim3 gFA(SS/128, BB*HH);

    for (int l = 0; l < LL; l++) {
        const __half* wqkv = wh + WQKV_OFF + (size_t)l * 3 * SZ_P;
        const __half* woh  = wh + WOT_OFF + (size_t)l * SZ_P;
        const __half* w1h  = wh + W1T_OFF + (size_t)l * SZ_F;
        const __half* w2h  = wh + W2T_OFF + (size_t)l * SZ_F;

        gemm_mma<128><<<gQKV, 256, GSM128>>>(xh, wqkv, bqkv + (size_t)l*NQKV,
                                             (float*)nullptr, qkv, DD, NQKV, 0);

        flash_attn<<<gFA, 256, FA_SMEM>>>(qkv, maskg, ch);

        if (l == 0) cudaStreamWaitEvent(0, evJoin, 0);

        gemm_mma<64><<<gWo, 256, GSM64>>>(ch, woh, bo + (size_t)l*DD,
                                          tmp, (__half*)nullptr, HDD, DD, 0);
        add_ln<<<MR, 256>>>(x, tmp, ln1g + (size_t)l*DD, ln1b + (size_t)l*DD, x, xh);

        gemm_mma<128><<<gF1, 256, GSM128>>>(xh, w1h, (const float*)nullptr,
                                            (float*)nullptr, fh, DD, FF, 1);
        gemm_mma<64><<<gF2, 256, GSM64>>>(fh, w2h, (const float*)nullptr,
                                          tmp, (__half*)nullptr, FF, DD, 0);

        float* dst = (l == LL - 1) ? out : x;
        __half* dsth = (l == LL - 1) ? (__half*)nullptr : xh;
        add_ln<<<MR, 256>>>(x, tmp, ln2g + (size_t)l*DD, ln2b + (size_t)l*DD, dst, dsth);
    }
}

// round 14
// speedup vs baseline: 1.0020x; 1.0020x over previous
#include <cuda_runtime.h>
#include <cuda_fp16.h>
#include <math.h>
#include <stdint.h>

#define BB   2
#define SS   1024
#define DD   1024
#define HH   16
#define HDD  1024
#define FF   4096
#define LL   4
#define MR   (BB*SS)
#define NQKV 3072

// -------------------- scratch --------------------
__device__ float g_x  [MR * DD];
__device__ float g_tmp[MR * DD];
__device__ float g_maskf[MR];
__device__ __half g_xh[MR * DD];
__device__ __half g_qkv[(size_t)MR * NQKV];
__device__ __half g_ch[MR * HDD];
__device__ __half g_fh[(size_t)MR * FF];
__device__ float g_bqkv[LL * NQKV];

#define SZ_P ((size_t)HDD * DD)
#define SZ_F ((size_t)DD * FF)
#define WQKV_OFF ((size_t)0)
#define WOT_OFF  ((size_t)LL * 3 * SZ_P)
#define W1T_OFF  (WOT_OFF + (size_t)LL * SZ_P)
#define W2T_OFF  (W1T_OFF + (size_t)LL * SZ_F)
#define WT_TOTAL (W2T_OFF + (size_t)LL * SZ_F)
__device__ __half g_wh[WT_TOTAL];

// ==================== helpers ====================
__device__ __forceinline__ uint32_t smem_to_u32(const void* p) {
    uint32_t a;
    asm("{ .reg .u64 t; cvta.to.shared.u64 t, %1; cvt.u32.u64 %0, t; }" : "=r"(a) : "l"(p));
    return a;
}
#define CP_ASYNC16(dst, src) \
    asm volatile("cp.async.cg.shared.global [%0], [%1], 16;" \
        :: "r"((uint32_t)(dst)), "l"(__cvta_generic_to_global(src)) : "memory")
#define CP_COMMIT() asm volatile("cp.async.commit_group;" ::: "memory")
#define CP_WAITG(n) asm volatile("cp.async.wait_group %0;" :: "n"(n) : "memory")
#define LDM_X4(r0, r1, r2, r3, addr) \
    asm volatile("ldmatrix.sync.aligned.m8n8.x4.shared.b16 {%0,%1,%2,%3}, [%4];" \
        : "=r"(r0), "=r"(r1), "=r"(r2), "=r"(r3) : "r"(addr))
#define LDM_X4_T(r0, r1, r2, r3, addr) \
    asm volatile("ldmatrix.sync.aligned.m8n8.x4.trans.shared.b16 {%0,%1,%2,%3}, [%4];" \
        : "=r"(r0), "=r"(r1), "=r"(r2), "=r"(r3) : "r"(addr))
#define MMA_F16(acc, a, b0, b1) \
    asm volatile("mma.sync.aligned.m16n8k16.row.col.f32.f16.f16.f32 " \
        "{%0,%1,%2,%3},{%4,%5,%6,%7},{%8,%9},{%0,%1,%2,%3};" \
        : "+f"((acc)[0]), "+f"((acc)[1]), "+f"((acc)[2]), "+f"((acc)[3]) \
        : "r"((a)[0]), "r"((a)[1]), "r"((a)[2]), "r"((a)[3]), "r"(b0), "r"(b1))

__device__ __forceinline__ uint32_t hpk2(float a, float b) {
    __half2 t = __floats2half2_rn(a, b);
    return *reinterpret_cast<uint32_t*>(&t);
}
__device__ __forceinline__ float gelu_f(float v) {
    float x = v * 0.70710678118654752f;
    float ax = fabsf(x);
    float t = __fdividef(1.0f, fmaf(0.3275911f, ax, 1.0f));
    float p = t * fmaf(t, fmaf(t, fmaf(t, fmaf(t, 1.061405429f, -1.453152027f),
                               1.421413741f), -0.284496736f), 0.254829592f);
    float erfv = 1.0f - p * __expf(-ax * ax);
    erfv = copysignf(erfv, x);
    return 0.5f * v * (1.0f + erfv);
}

// ==================== batched weight transpose ====================
__device__ __forceinline__ void tsplit_body(
    const float* __restrict__ W, __half* __restrict__ th, int K, int N)
{
    __shared__ float ts[64][65];
    const int n0 = blockIdx.x * 64, k0 = blockIdx.y * 64;
    const int tid = threadIdx.x;
    #pragma unroll
    for (int i = 0; i < 4; i++) {
        int e = tid + i * 256;
        int r = e >> 4, c4 = (e & 15) * 4;
        float4 v = *(const float4*)&W[(size_t)(k0 + r) * N + n0 + c4];
        ts[r][c4]     = v.x; ts[r][c4 + 1] = v.y;
        ts[r][c4 + 2] = v.z; ts[r][c4 + 3] = v.w;
    }
    __syncthreads();
    const int w = tid >> 5, lane = tid & 31;
    #pragma unroll
    for (int rr = 0; rr < 8; rr++) {
        int n = w * 8 + rr;
        float a = ts[lane * 2][n], b = ts[lane * 2 + 1][n];
        size_t o = (size_t)(n0 + n) * K + k0 + lane * 2;
        *(uint32_t*)&th[o] = hpk2(a, b);
    }
}

__global__ __launch_bounds__(256) void tsplit_qkv(
    const float* __restrict__ Wq, const float* __restrict__ Wk,
    const float* __restrict__ Wv, __half* __restrict__ th)
{
    int z = blockIdx.z;
    int l = z / 3, j = z - l * 3;
    const float* W = ((j == 0) ? Wq : (j == 1) ? Wk : Wv) + (size_t)l * SZ_P;
    __half* dst = th + ((size_t)l * 3 + j) * SZ_P;
    tsplit_body(W, dst, DD, HDD);
}

__global__ __launch_bounds__(256) void tsplit_b(
    const float* __restrict__ W, __half* __restrict__ th, int K, int N)
{
    size_t off = (size_t)blockIdx.z * K * N;
    tsplit_body(W + off, th + off, K, N);
}

__global__ void biascat_kernel(const float* __restrict__ bq, const float* __restrict__ bk,
                               const float* __restrict__ bv, float* __restrict__ o)
{
    int i = blockIdx.x * 256 + threadIdx.x;
    int l = i / NQKV, r = i % NQKV;
    int seg = r >> 10, n = r & 1023;
    const float* s = (seg == 0) ? bq : (seg == 1) ? bk : bv;
    o[i] = s[l * 1024 + n];
}

__global__ void mask_kernel(const int* __restrict__ tok, float* __restrict__ m)
{
    int i = blockIdx.x * 256 + threadIdx.x;
    m[i] = (tok[i] == 0) ? -1e9f : 0.f;
}

// ==================== fp16 HMMA GEMM, single-barrier 4-slot pipeline (d<=S-2) ====================
#define KC 32
#define ARR_B 10240

template<int MT>
__global__ __launch_bounds__(256, 2) void gemm_mma(
    const __half* __restrict__ A, const __half* __restrict__ B,
    const float* __restrict__ bias, float* __restrict__ C,
    __half* __restrict__ Ch, int K, int N, int act)
{
    constexpr uint32_t ARR_A = (uint32_t)MT * 80;
    constexpr uint32_t STGB  = ARR_A + ARR_B;
    constexpr int AITER = MT / 64;
    constexpr int NFRAG = (MT == 128) ? 8 : 4;
    constexpr int NB    = NFRAG / 2;
    constexpr int WNW   = (MT == 128) ? 64 : 32;

    extern __shared__ __align__(128) char smem_raw[];
    const uint32_t sbase = smem_to_u32(smem_raw);

    const int tid  = threadIdx.x;
    const int lane = tid & 31;
    const int wid  = tid >> 5;
    const int wm   = (MT == 128) ? (wid & 3) : (wid & 1);
    const int wn   = (MT == 128) ? (wid >> 2) : (wid >> 1);
    const int m0 = blockIdx.y * MT, n0 = blockIdx.x * 128;

    float acc[2][NFRAG][4];
    #pragma unroll
    for (int i = 0; i < 2; i++)
        #pragma unroll
        for (int j = 0; j < NFRAG; j++)
            #pragma unroll
            for (int q2 = 0; q2 < 4; q2++) acc[i][j][q2] = 0.f;

    const int nc = K >> 5;

    #define FILL_STAGE(stg, kk) do { \
        const uint32_t so_ = sbase + (uint32_t)(stg) * STGB; \
        _Pragma("unroll") \
        for (int i_ = 0; i_ < AITER + 2; i_++) { \
            const int isA_ = (i_ < AITER); \
            int rem_ = (isA_ ? i_ : (i_ - AITER)) * 256 + tid; \
            int row_ = rem_ >> 2, seg_ = rem_ & 3; \
            const __half* p_ = isA_ ? A : B; \
            int rb_ = isA_ ? m0 : n0; \
            uint32_t dst_ = so_ + (isA_ ? 0u : ARR_A) + row_ * 80 + seg_ * 16; \
            CP_ASYNC16(dst_, p_ + (size_t)(rb_ + row_) * K + (kk) + seg_ * 8); \
        } \
        CP_COMMIT(); \
    } while (0)

    FILL_STAGE(0, 0);
    FILL_STAGE(1, KC);

    const uint32_t lrow  = lane & 15;
    const uint32_t khalf = lane >> 4;
    const uint32_t a_row_off = (wm * 32 + lrow) * 80;
    const uint32_t b_row_off = (wn * WNW + lrow) * 80;

    for (int c = 0; c < nc; c++) {
        if (c + 2 < nc) { FILL_STAGE((c + 2) & 3, (c + 2) * KC); CP_WAITG(2); }
        else if (c + 1 < nc) CP_WAITG(1);
        else CP_WAITG(0);
        __syncthreads();

        const uint32_t so = sbase + (uint32_t)(c & 3) * STGB;
        const uint32_t sA = so, sB = so + ARR_A;

        #pragma unroll
        for (int ks = 0; ks < 2; ks++) {
            const uint32_t kofs = (ks * 16 + khalf * 8) * 2;
            uint32_t af[2][4];
            #pragma unroll
            for (int mb = 0; mb < 2; mb++) {
                uint32_t ad = a_row_off + mb * 16 * 80 + kofs;
                LDM_X4(af[mb][0], af[mb][1], af[mb][2], af[mb][3], sA + ad);
            }
            #pragma unroll
            for (int nb = 0; nb < NB; nb++) {
                uint32_t bd = b_row_off + nb * 16 * 80 + kofs;
                uint32_t bf_[4];
                LDM_X4(bf_[0], bf_[1], bf_[2], bf_[3], sB + bd);
                #pragma unroll
                for (int mb = 0; mb < 2; mb++) {
                    MMA_F16(acc[mb][nb * 2],     af[mb], bf_[0], bf_[2]);
                    MMA_F16(acc[mb][nb * 2 + 1], af[mb], bf_[1], bf_[3]);
                }
            }
        }
    }
    #undef FILL_STAGE

    const int mrow = m0 + wm * 32 + (lane >> 2);
    const int ncol0 = n0 + wn * WNW + (lane & 3) * 2;
    #pragma unroll
    for (int mb = 0; mb < 2; mb++) {
        #pragma unroll
        for (int nf = 0; nf < NFRAG; nf++) {
            int n = ncol0 + nf * 8;
            float b0v = bias ? bias[n]     : 0.f;
            float b1v = bias ? bias[n + 1] : 0.f;
            float v0 = acc[mb][nf][0] + b0v;
            float v1 = acc[mb][nf][1] + b1v;
            float v2 = acc[mb][nf][2] + b0v;
            float v3 = acc[mb][nf][3] + b1v;
            if (act) { v0 = gelu_f(v0); v1 = gelu_f(v1); v2 = gelu_f(v2); v3 = gelu_f(v3); }
            int m = mrow + mb * 16;
            if (C) {
                *(float2*)(C + (size_t)m * N + n)       = make_float2(v0, v1);
                *(float2*)(C + (size_t)(m + 8) * N + n) = make_float2(v2, v3);
            }
            if (Ch) {
                *(uint32_t*)(Ch + (size_t)m * N + n)       = hpk2(v0, v1);
                *(uint32_t*)(Ch + (size_t)(m + 8) * N + n) = hpk2(v2, v3);
            }
        }
    }
}

// ==================== flash attention (fp16, 64-key tiles, 4-stage, race-free) ====================
#define FA_Q     0
#define FA_STG0  18432
#define FA_K     0
#define FA_V     9216
#define FA_MSK   18432
#define FA_STGSZ 18688
#define FA_SMEM  (18432 + 4 * 18688)   // 93184

__global__ __launch_bounds__(256, 2) void flash_attn(
    const __half* __restrict__ qkv, const float* __restrict__ maskg,
    __half* __restrict__ ch)
{
    extern __shared__ __align__(128) char smem_raw[];
    const uint32_t base = smem_to_u32(smem_raw);
    const uint32_t sQ = base + FA_Q;

    const int tid = threadIdx.x, lane = tid & 31, wid = tid >> 5;
    const int q0 = blockIdx.x * 128;
    const int z = blockIdx.y, b = z >> 4, h = z & 15;
    const uint32_t lrow = lane & 15, khalf = lane >> 4;
    const int cpos = (lane & 3) * 2;
    const int colQ = h * 64, colK = 1024 + h * 64, colV = 2048 + h * 64;

    #pragma unroll
    for (int i = 0; i < 2; i++) {
        int idx = tid + i * 256;
        int row = idx >> 2, seg2 = (idx & 3) * 2;
        size_t src = (size_t)(b * SS + q0 + row) * NQKV + colQ + seg2 * 8;
        CP_ASYNC16(sQ + row * 144 + seg2 * 16, qkv + src);
        CP_ASYNC16(sQ + row * 144 + seg2 * 16 + 16, qkv + src + 8);
    }
    CP_COMMIT();

    #define FA_FILL(kt_) do { \
        const int stg_ = (kt_) & 3; \
        const uint32_t sb_ = base + FA_STG0 + stg_ * FA_STGSZ; \
        const int k0_ = (kt_) * 64; \
        { int row_ = tid >> 2, s2_ = tid & 3; \
          size_t srck_ = (size_t)(b * SS + k0_ + row_) * NQKV + colK + s2_ * 16; \
          uint32_t dstk_ = sb_ + FA_K + row_ * 144 + s2_ * 32; \
          CP_ASYNC16(dstk_, qkv + srck_); \
          CP_ASYNC16(dstk_ + 16, qkv + srck_ + 8); \
          size_t srcv_ = (size_t)(b * SS + k0_ + row_) * NQKV + colV + s2_ * 16; \
          uint32_t dstv_ = sb_ + FA_V + row_ * 144 + s2_ * 32; \
          CP_ASYNC16(dstv_, qkv + srcv_); \
          CP_ASYNC16(dstv_ + 16, qkv + srcv_ + 8); } \
        if (tid < 16) \
            CP_ASYNC16(sb_ + FA_MSK + tid * 16, maskg + b * SS + k0_ + tid * 4); \
        CP_COMMIT(); \
    } while (0)

    FA_FILL(0);
    FA_FILL(1);

    // hoist Q fragment load: wait only the Q group (2 newer groups pending)
    uint32_t qf[4][4];
    CP_WAITG(2);
    __syncthreads();
    #pragma unroll
    for (int ks = 0; ks < 4; ks++) {
        uint32_t ad = (wid * 16 + lrow) * 144 + (ks * 16 + khalf * 8) * 2;
        LDM_X4(qf[ks][0], qf[ks][1], qf[ks][2], qf[ks][3], sQ + ad);
    }

    float m0 = -3.0e38f, m1 = -3.0e38f, l0 = 0.f, l1 = 0.f;
    float O[8][4];
    #pragma unroll
    for (int i = 0; i < 8; i++)
        #pragma unroll
        for (int j = 0; j < 4; j++) O[i][j] = 0.f;

    for (int kt = 0; kt < 16; kt++) {
        if (kt + 2 < 16) { FA_FILL(kt + 2); CP_WAITG(2); }
        else if (kt + 1 < 16) CP_WAITG(1);
        else CP_WAITG(0);
        __syncthreads();

        const uint32_t sb = base + FA_STG0 + (uint32_t)(kt & 3) * FA_STGSZ;
        const uint32_t sK = sb + FA_K, sV = sb + FA_V;
        const float* maskf = (const float*)(smem_raw + FA_STG0 + (kt & 3) * FA_STGSZ + FA_MSK);

        float Sv[8][4];
        #pragma unroll
        for (int i = 0; i < 8; i++)
            #pragma unroll
            for (int j = 0; j < 4; j++) Sv[i][j] = 0.f;

        #pragma unroll
        for (int ks = 0; ks < 4; ks++) {
            #pragma unroll
            for (int ng = 0; ng < 4; ng++) {
                uint32_t bd = (ng * 16 + lrow) * 144 + (ks * 16 + khalf * 8) * 2;
                uint32_t bh_[4];
                LDM_X4(bh_[0], bh_[1], bh_[2], bh_[3], sK + bd);
                MMA_F16(Sv[2 * ng],     qf[ks], bh_[0], bh_[2]);
                MMA_F16(Sv[2 * ng + 1], qf[ks], bh_[1], bh_[3]);
            }
        }

        float mt0 = -3.0e38f, mt1 = -3.0e38f;
        #pragma unroll
        for (int nb = 0; nb < 8; nb++) {
            float mk0 = maskf[nb * 8 + cpos], mk1 = maskf[nb * 8 + cpos + 1];
            Sv[nb][0] = Sv[nb][0] * 0.125f + mk0;
            Sv[nb][1] = Sv[nb][1] * 0.125f + mk1;
            Sv[nb][2] = Sv[nb][2] * 0.125f + mk0;
            Sv[nb][3] = Sv[nb][3] * 0.125f + mk1;
            mt0 = fmaxf(mt0, fmaxf(Sv[nb][0], Sv[nb][1]));
            mt1 = fmaxf(mt1, fmaxf(Sv[nb][2], Sv[nb][3]));
        }
        mt0 = fmaxf(mt0, __shfl_xor_sync(0xffffffffu, mt0, 1));
        mt0 = fmaxf(mt0, __shfl_xor_sync(0xffffffffu, mt0, 2));
        mt1 = fmaxf(mt1, __shfl_xor_sync(0xffffffffu, mt1, 1));
        mt1 = fmaxf(mt1, __shfl_xor_sync(0xffffffffu, mt1, 2));

        float mn0 = fmaxf(m0, mt0), mn1 = fmaxf(m1, mt1);
        float al0 = __expf(m0 - mn0), al1 = __expf(m1 - mn1);
        float su0 = 0.f, su1 = 0.f;
        #pragma unroll
        for (int nb = 0; nb < 8; nb++) {
            Sv[nb][0] = __expf(Sv[nb][0] - mn0);
            Sv[nb][1] = __expf(Sv[nb][1] - mn0);
            Sv[nb][2] = __expf(Sv[nb][2] - mn1);
            Sv[nb][3] = __expf(Sv[nb][3] - mn1);
            su0 += Sv[nb][0] + Sv[nb][1];
            su1 += Sv[nb][2] + Sv[nb][3];
        }
        su0 += __shfl_xor_sync(0xffffffffu, su0, 1);
        su0 += __shfl_xor_sync(0xffffffffu, su0, 2);
        su1 += __shfl_xor_sync(0xffffffffu, su1, 1);
        su1 += __shfl_xor_sync(0xffffffffu, su1, 2);

        l0 = l0 * al0 + su0;
        l1 = l1 * al1 + su1;
        m0 = mn0; m1 = mn1;
        #pragma unroll
        for (int nf = 0; nf < 8; nf++) {
            O[nf][0] *= al0; O[nf][1] *= al0;
            O[nf][2] *= al1; O[nf][3] *= al1;
        }

        #pragma unroll
        for (int j = 0; j < 4; j++) {
            uint32_t pa[4];
            pa[0] = hpk2(Sv[2*j][0],   Sv[2*j][1]);
            pa[1] = hpk2(Sv[2*j][2],   Sv[2*j][3]);
            pa[2] = hpk2(Sv[2*j+1][0], Sv[2*j+1][1]);
            pa[3] = hpk2(Sv[2*j+1][2], Sv[2*j+1][3]);
            #pragma unroll
            for (int ng = 0; ng < 4; ng++) {
                uint32_t bd = sV + (j * 16 + lrow) * 144 + (ng * 16 + khalf * 8) * 2;
                uint32_t v0, v1, v2, v3;
                LDM_X4_T(v0, v1, v2, v3, bd);
                MMA_F16(O[2 * ng],     pa, v0, v1);
                MMA_F16(O[2 * ng + 1], pa, v2, v3);
            }
        }
    }
    #undef FA_FILL

    float i0 = 1.f / l0, i1 = 1.f / l1;
    const int rgl = b * SS + q0 + wid * 16 + (lane >> 2);
    #pragma unroll
    for (int nf = 0; nf < 8; nf++) {
        int col = h * 64 + nf * 8 + cpos;
        size_t o0 = (size_t)rgl * HDD + col;
        size_t o1 = (size_t)(rgl + 8) * HDD + col;
        *(uint32_t*)(ch + o0) = hpk2(O[nf][0] * i0, O[nf][1] * i0);
        *(uint32_t*)(ch + o1) = hpk2(O[nf][2] * i1, O[nf][3] * i1);
    }
}

// ==================== embed + add_ln ====================
__global__ __launch_bounds__(256) void embed_kernel(
    const int* __restrict__ tok, const float* __restrict__ emb,
    float* __restrict__ x, __half* __restrict__ xh)
{
    int row = blockIdx.x;
    int s = row % SS;
    int t = tok[row];
    const float* e = emb + (size_t)t * DD;
    for (int d = threadIdx.x; d < DD; d += 256) {
        int i = d >> 1;
        float freq = expf(-((float)(2 * i) / (float)DD) * 9.210340371976184f);
        float a = (float)s * freq;
        float pe = (d & 1) ? cosf(a) : sinf(a);
        float v = e[d] + pe;
        size_t o = (size_t)row * DD + d;
        x[o] = v;
        xh[o] = __float2half_rn(v);
    }
}

__device__ __forceinline__ float block_sum(float v, float* sh) {
    __syncthreads();
    #pragma unroll
    for (int o = 16; o > 0; o >>= 1) v += __shfl_xor_sync(0xffffffffu, v, o);
    int w = threadIdx.x >> 5;
    if ((threadIdx.x & 31) == 0) sh[w] = v;
    __syncthreads();
    float t = (threadIdx.x < 8) ? sh[threadIdx.x] : 0.0f;
    #pragma unroll
    for (int o = 4; o > 0; o >>= 1) t += __shfl_xor_sync(0xffffffffu, t, o);
    if (threadIdx.x == 0) sh[0] = t;
    __syncthreads();
    return sh[0];
}

__global__ __launch_bounds__(256) void add_ln(
    const float* __restrict__ xin, const float* __restrict__ delta,
    const float* __restrict__ g, const float* __restrict__ bta,
    float* __restrict__ out, __half* __restrict__ oh)
{
    size_t row = blockIdx.x;
    const float* xr = xin   + row * DD;
    const float* dr = delta + row * DD;
    int tid = threadIdx.x;
    __shared__ float red[8];

    float v[4];
    float s = 0.f;
    #pragma unroll
    for (int j = 0; j < 4; j++) {
        int c = tid + j * 256;
        v[j] = xr[c] + dr[c];
        s += v[j];
    }
    s = block_sum(s, red);
    float mu = s * (1.0f / 1024.0f);
    float var = 0.f;
    #pragma unroll
    for (int j = 0; j < 4; j++) { float t = v[j] - mu; var += t * t; }
    var = block_sum(var, red) * (1.0f / 1024.0f);
    float inv = rsqrtf(var + 1e-5f);
    #pragma unroll
    for (int j = 0; j < 4; j++) {
        int c = tid + j * 256;
        float o = (v[j] - mu) * inv * g[c] + bta[c];
        size_t idx = row * DD + c;
        out[idx] = o;
        if (oh) oh[idx] = __float2half_rn(o);
    }
}

// ==================== host orchestration ====================
extern "C" void kernel_launch(void* const* d_in, const int* in_sizes, int n_in,
                              void* d_out, int out_size)
{
    (void)in_sizes; (void)n_in; (void)out_size;
    const int*   tok  = (const int*)  d_in[0];
    const float* emb  = (const float*)d_in[1];
    const float* Wq   = (const float*)d_in[2];
    const float* bq   = (const float*)d_in[3];
    const float* Wk   = (const float*)d_in[4];
    const float* bk   = (const float*)d_in[5];
    const float* Wv   = (const float*)d_in[6];
    const float* bv   = (const float*)d_in[7];
    const float* Wo   = (const float*)d_in[8];
    const float* bo   = (const float*)d_in[9];
    const float* ln1g = (const float*)d_in[10];
    const float* ln1b = (const float*)d_in[11];
    const float* W1   = (const float*)d_in[12];
    const float* W2   = (const float*)d_in[13];
    const float* ln2g = (const float*)d_in[14];
    const float* ln2b = (const float*)d_in[15];
    float* out = (float*)d_out;

    float *x, *tmp, *bqkv, *maskg;
    __half *xh, *qkv, *ch, *fh, *wh;
    cudaGetSymbolAddress((void**)&x,     g_x);
    cudaGetSymbolAddress((void**)&tmp,   g_tmp);
    cudaGetSymbolAddress((void**)&maskg, g_maskf);
    cudaGetSymbolAddress((void**)&xh,    g_xh);
    cudaGetSymbolAddress((void**)&qkv,   g_qkv);
    cudaGetSymbolAddress((void**)&ch,    g_ch);
    cudaGetSymbolAddress((void**)&fh,    g_fh);
    cudaGetSymbolAddress((void**)&wh,    g_wh);
    cudaGetSymbolAddress((void**)&bqkv,  g_bqkv);

    const int GSM128 = 4 * (128 * 80 + ARR_B);   // 81920
    const int GSM64  = 4 * (64 * 80 + ARR_B);    // 61440

    static int attr_done = 0;
    static cudaStream_t s2;
    static cudaEvent_t evFork, evPrep, evJoin;
    if (!attr_done) {
        cudaFuncSetAttribute(gemm_mma<128>, cudaFuncAttributeMaxDynamicSharedMemorySize, GSM128);
        cudaFuncSetAttribute(gemm_mma<64>,  cudaFuncAttributeMaxDynamicSharedMemorySize, GSM64);
        cudaFuncSetAttribute(flash_attn, cudaFuncAttributeMaxDynamicSharedMemorySize, FA_SMEM);
        cudaStreamCreateWithFlags(&s2, cudaStreamNonBlocking);
        cudaEventCreateWithFlags(&evFork, cudaEventDisableTiming);
        cudaEventCreateWithFlags(&evPrep, cudaEventDisableTiming);
        cudaEventCreateWithFlags(&evJoin, cudaEventDisableTiming);
        attr_done = 1;
    }

    // fork immediately: prep pipeline split across two streams
    cudaEventRecord(evFork, 0);
    cudaStreamWaitEvent(s2, evFork, 0);

    // s0: embed (needed for QKV gemm)
    embed_kernel<<<MR, 256>>>(tok, emb, x, xh);

    // s2: mask + biascat + tsplit_qkv (needed for QKV gemm / flash), then Wo/W1/W2
    mask_kernel<<<MR / 256, 256, 0, s2>>>(tok, maskg);
    biascat_kernel<<<LL * NQKV / 256, 256, 0, s2>>>(bq, bk, bv, bqkv);
    tsplit_qkv<<<dim3(HDD/64, DD/64, LL*3), 256, 0, s2>>>(Wq, Wk, Wv, wh + WQKV_OFF);
    cudaEventRecord(evPrep, s2);
    tsplit_b<<<dim3(DD/64, HDD/64, LL), 256, 0, s2>>>(Wo, wh + WOT_OFF, HDD, DD);
    tsplit_b<<<dim3(FF/64, DD/64, LL), 256, 0, s2>>>(W1, wh + W1T_OFF, DD, FF);
    tsplit_b<<<dim3(DD/64, FF/64, LL), 256, 0, s2>>>(W2, wh + W2T_OFF, FF, DD);
    cudaEventRecord(evJoin, s2);

    // join: QKV gemm needs xh (s0) + wqkv/bqkv (s2); flash needs maskg (s2)
    cudaStreamWaitEvent(0, evPrep, 0);

    dim3 gQKV(NQKV/128, MR/128);   // MT=128
    dim3 gWo(DD/128, MR/64);       // MT=64
    dim3 gF1(FF/128, MR/128);      // MT=128
    dim3 gF2(DD/128, MR/64);       // MT=64
    dim3 gFA(SS/128, BB*HH);

    for (int l = 0; l < LL; l++) {
        const __half* wqkv = wh + WQKV_OFF + (size_t)l * 3 * SZ_P;
        const __half* woh  = wh + WOT_OFF + (size_t)l * SZ_P;
        const __half* w1h  = wh + W1T_OFF + (size_t)l * SZ_F;
        const __half* w2h  = wh + W2T_OFF + (size_t)l * SZ_F;

        gemm_mma<128><<<gQKV, 256, GSM128>>>(xh, wqkv, bqkv + (size_t)l*NQKV,
                                             (float*)nullptr, qkv, DD, NQKV, 0);

        flash_attn<<<gFA, 256, FA_SMEM>>>(qkv, maskg, ch);

        if (l == 0) cudaStreamWaitEvent(0, evJoin, 0);

        gemm_mma<64><<<gWo, 256, GSM64>>>(ch, woh, bo + (size_t)l*DD,
                                          tmp, (__half*)nullptr, HDD, DD, 0);
        add_ln<<<MR, 256>>>(x, tmp, ln1g + (size_t)l*DD, ln1b + (size_t)l*DD, x, xh);

        gemm_mma<128><<<gF1, 256, GSM128>>>(xh, w1h, (const float*)nullptr,
                                            (float*)nullptr, fh, DD, FF, 1);
        gemm_mma<64><<<gF2, 256, GSM64>>>(fh, w2h, (const float*)nullptr,
                                          tmp, (__half*)nullptr, FF, DD, 0);

        float* dst = (l == LL - 1) ? out : x;
        __half* dsth = (l == LL - 1) ? (__half*)nullptr : xh;
        add_ln<<<MR, 256>>>(x, tmp, ln2g + (size_t)l*DD, ln2b + (size_t)l*DD, dst, dsth);
    }
}

// round 15
// speedup vs baseline: 1.0996x; 1.0974x over previous
#include <cuda_runtime.h>
#include <cuda_fp16.h>
#include <math.h>
#include <stdint.h>

#define BB   2
#define SS   1024
#define DD   1024
#define HH   16
#define HDD  1024
#define FF   4096
#define LL   4
#define MR   (BB*SS)
#define NQKV 3072

// -------------------- scratch --------------------
__device__ float g_x  [MR * DD];
__device__ float g_tmp[MR * DD];
__device__ __half g_xh[MR * DD];
__device__ __half g_qkv[(size_t)MR * NQKV];
__device__ __half g_ch[MR * HDD];
__device__ __half g_fh[(size_t)MR * FF];
__device__ float g_bqkv[LL * NQKV];

#define SZ_P ((size_t)HDD * DD)
#define SZ_F ((size_t)DD * FF)
#define WQKV_OFF ((size_t)0)
#define WOT_OFF  ((size_t)LL * 3 * SZ_P)
#define W1T_OFF  (WOT_OFF + (size_t)LL * SZ_P)
#define W2T_OFF  (W1T_OFF + (size_t)LL * SZ_F)
#define WT_TOTAL (W2T_OFF + (size_t)LL * SZ_F)
__device__ __half g_wh[WT_TOTAL];

// ==================== helpers ====================
__device__ __forceinline__ uint32_t smem_to_u32(const void* p) {
    uint32_t a;
    asm("{ .reg .u64 t; cvta.to.shared.u64 t, %1; cvt.u32.u64 %0, t; }" : "=r"(a) : "l"(p));
    return a;
}
#define CP_ASYNC16(dst, src) \
    asm volatile("cp.async.cg.shared.global [%0], [%1], 16;" \
        :: "r"((uint32_t)(dst)), "l"(__cvta_generic_to_global(src)) : "memory")
#define CP_COMMIT() asm volatile("cp.async.commit_group;" ::: "memory")
#define CP_WAITG(n) asm volatile("cp.async.wait_group %0;" :: "n"(n) : "memory")
#define LDM_X4(r0, r1, r2, r3, addr) \
    asm volatile("ldmatrix.sync.aligned.m8n8.x4.shared.b16 {%0,%1,%2,%3}, [%4];" \
        : "=r"(r0), "=r"(r1), "=r"(r2), "=r"(r3) : "r"(addr))
#define LDM_X4_T(r0, r1, r2, r3, addr) \
    asm volatile("ldmatrix.sync.aligned.m8n8.x4.trans.shared.b16 {%0,%1,%2,%3}, [%4];" \
        : "=r"(r0), "=r"(r1), "=r"(r2), "=r"(r3) : "r"(addr))
#define MMA_F16(acc, a, b0, b1) \
    asm volatile("mma.sync.aligned.m16n8k16.row.col.f32.f16.f16.f32 " \
        "{%0,%1,%2,%3},{%4,%5,%6,%7},{%8,%9},{%0,%1,%2,%3};" \
        : "+f"((acc)[0]), "+f"((acc)[1]), "+f"((acc)[2]), "+f"((acc)[3]) \
        : "r"((a)[0]), "r"((a)[1]), "r"((a)[2]), "r"((a)[3]), "r"(b0), "r"(b1))

__device__ __forceinline__ uint32_t hpk2(float a, float b) {
    __half2 t = __floats2half2_rn(a, b);
    return *reinterpret_cast<uint32_t*>(&t);
}
__device__ __forceinline__ float gelu_f(float v) {
    float x = v * 0.70710678118654752f;
    float ax = fabsf(x);
    float t = __fdividef(1.0f, fmaf(0.3275911f, ax, 1.0f));
    float p = t * fmaf(t, fmaf(t, fmaf(t, fmaf(t, 1.061405429f, -1.453152027f),
                               1.421413741f), -0.284496736f), 0.254829592f);
    float erfv = 1.0f - p * __expf(-ax * ax);
    erfv = copysignf(erfv, x);
    return 0.5f * v * (1.0f + erfv);
}

// ==================== batched weight transpose ====================
__device__ __forceinline__ void tsplit_body(
    const float* __restrict__ W, __half* __restrict__ th, int K, int N)
{
    __shared__ float ts[64][65];
    const int n0 = blockIdx.x * 64, k0 = blockIdx.y * 64;
    const int tid = threadIdx.x;
    #pragma unroll
    for (int i = 0; i < 4; i++) {
        int e = tid + i * 256;
        int r = e >> 4, c4 = (e & 15) * 4;
        float4 v = *(const float4*)&W[(size_t)(k0 + r) * N + n0 + c4];
        ts[r][c4]     = v.x; ts[r][c4 + 1] = v.y;
        ts[r][c4 + 2] = v.z; ts[r][c4 + 3] = v.w;
    }
    __syncthreads();
    const int w = tid >> 5, lane = tid & 31;
    #pragma unroll
    for (int rr = 0; rr < 8; rr++) {
        int n = w * 8 + rr;
        float a = ts[lane * 2][n], b = ts[lane * 2 + 1][n];
        size_t o = (size_t)(n0 + n) * K + k0 + lane * 2;
        *(uint32_t*)&th[o] = hpk2(a, b);
    }
}

__global__ __launch_bounds__(256) void tsplit_qkv(
    const float* __restrict__ Wq, const float* __restrict__ Wk,
    const float* __restrict__ Wv, __half* __restrict__ th)
{
    int z = blockIdx.z;
    int l = z / 3, j = z - l * 3;
    const float* W = ((j == 0) ? Wq : (j == 1) ? Wk : Wv) + (size_t)l * SZ_P;
    __half* dst = th + ((size_t)l * 3 + j) * SZ_P;
    tsplit_body(W, dst, DD, HDD);
}

__global__ __launch_bounds__(256) void tsplit_b(
    const float* __restrict__ W, __half* __restrict__ th, int K, int N)
{
    size_t off = (size_t)blockIdx.z * K * N;
    tsplit_body(W + off, th + off, K, N);
}

__global__ void biascat_kernel(const float* __restrict__ bq, const float* __restrict__ bk,
                               const float* __restrict__ bv, float* __restrict__ o)
{
    int i = blockIdx.x * 256 + threadIdx.x;
    int l = i / NQKV, r = i % NQKV;
    int seg = r >> 10, n = r & 1023;
    const float* s = (seg == 0) ? bq : (seg == 1) ? bk : bv;
    o[i] = s[l * 1024 + n];
}

// ==================== fp16 HMMA GEMM, KC=64, 3-slot d=1 pipeline (d<=S-2) ====================
#define KCB 64                       // k-elements per chunk (128 bytes)
#define SPB 144                      // smem row stride bytes (128 + 16 pad)
#define ARR_BB (128 * SPB)           // 18432 B (B tile rows)

template<int MT>
__global__ __launch_bounds__(256, 2) void gemm_mma(
    const __half* __restrict__ A, const __half* __restrict__ B,
    const float* __restrict__ bias, float* __restrict__ C,
    __half* __restrict__ Ch, int K, int N, int act)
{
    constexpr uint32_t ARR_A = (uint32_t)MT * SPB;
    constexpr uint32_t STGB  = ARR_A + ARR_BB;
    constexpr int AIT  = MT / 32;           // A fill iters (8 segs/row)
    constexpr int NFRAG = (MT == 128) ? 8 : 4;
    constexpr int NB    = NFRAG / 2;
    constexpr int WNW   = (MT == 128) ? 64 : 32;

    extern __shared__ __align__(128) char smem_raw[];
    const uint32_t sbase = smem_to_u32(smem_raw);

    const int tid  = threadIdx.x;
    const int lane = tid & 31;
    const int wid  = tid >> 5;
    const int wm   = (MT == 128) ? (wid & 3) : (wid & 1);
    const int wn   = (MT == 128) ? (wid >> 2) : (wid >> 1);
    const int m0 = blockIdx.y * MT, n0 = blockIdx.x * 128;

    float acc[2][NFRAG][4];
    #pragma unroll
    for (int i = 0; i < 2; i++)
        #pragma unroll
        for (int j = 0; j < NFRAG; j++)
            #pragma unroll
            for (int q2 = 0; q2 < 4; q2++) acc[i][j][q2] = 0.f;

    const int nc = K >> 6;    // K / 64

    #define FILL_STAGE(stg, kk) do { \
        const uint32_t so_ = sbase + (uint32_t)(stg) * STGB; \
        _Pragma("unroll") \
        for (int i_ = 0; i_ < AIT + 4; i_++) { \
            const int isA_ = (i_ < AIT); \
            int rem_ = (isA_ ? i_ : (i_ - AIT)) * 256 + tid; \
            int row_ = rem_ >> 3, seg_ = rem_ & 7; \
            const __half* p_ = isA_ ? A : B; \
            int rb_ = isA_ ? m0 : n0; \
            uint32_t dst_ = so_ + (isA_ ? 0u : ARR_A) + row_ * SPB + seg_ * 16; \
            CP_ASYNC16(dst_, p_ + (size_t)(rb_ + row_) * K + (kk) + seg_ * 8); \
        } \
        CP_COMMIT(); \
    } while (0)

    FILL_STAGE(0, 0);

    const uint32_t lrow  = lane & 15;
    const uint32_t khalf = lane >> 4;
    const uint32_t a_row_off = (wm * 32 + lrow) * SPB;
    const uint32_t b_row_off = (wn * WNW + lrow) * SPB;

    int slot = 0, fslot = 1;
    for (int c = 0; c < nc; c++) {
        if (c + 1 < nc) {
            FILL_STAGE(fslot, (c + 1) * KCB);
            fslot = (fslot == 2) ? 0 : fslot + 1;
            CP_WAITG(1);
        } else {
            CP_WAITG(0);
        }
        __syncthreads();

        const uint32_t so = sbase + (uint32_t)slot * STGB;
        slot = (slot == 2) ? 0 : slot + 1;
        const uint32_t sA = so, sB = so + ARR_A;

        #pragma unroll
        for (int ks = 0; ks < 4; ks++) {
            const uint32_t kofs = ks * 32 + khalf * 16;
            uint32_t af[2][4];
            #pragma unroll
            for (int mb = 0; mb < 2; mb++) {
                uint32_t ad = a_row_off + mb * 16 * SPB + kofs;
                LDM_X4(af[mb][0], af[mb][1], af[mb][2], af[mb][3], sA + ad);
            }
            #pragma unroll
            for (int nb = 0; nb < NB; nb++) {
                uint32_t bd = b_row_off + nb * 16 * SPB + kofs;
                uint32_t bf_[4];
                LDM_X4(bf_[0], bf_[1], bf_[2], bf_[3], sB + bd);
                #pragma unroll
                for (int mb = 0; mb < 2; mb++) {
                    MMA_F16(acc[mb][nb * 2],     af[mb], bf_[0], bf_[2]);
                    MMA_F16(acc[mb][nb * 2 + 1], af[mb], bf_[1], bf_[3]);
                }
            }
        }
    }
    #undef FILL_STAGE

    const int mrow = m0 + wm * 32 + (lane >> 2);
    const int ncol0 = n0 + wn * WNW + (lane & 3) * 2;
    #pragma unroll
    for (int mb = 0; mb < 2; mb++) {
        #pragma unroll
        for (int nf = 0; nf < NFRAG; nf++) {
            int n = ncol0 + nf * 8;
            float b0v = bias ? bias[n]     : 0.f;
            float b1v = bias ? bias[n + 1] : 0.f;
            float v0 = acc[mb][nf][0] + b0v;
            float v1 = acc[mb][nf][1] + b1v;
            float v2 = acc[mb][nf][2] + b0v;
            float v3 = acc[mb][nf][3] + b1v;
            if (act) { v0 = gelu_f(v0); v1 = gelu_f(v1); v2 = gelu_f(v2); v3 = gelu_f(v3); }
            int m = mrow + mb * 16;
            if (C) {
                *(float2*)(C + (size_t)m * N + n)       = make_float2(v0, v1);
                *(float2*)(C + (size_t)(m + 8) * N + n) = make_float2(v2, v3);
            }
            if (Ch) {
                *(uint32_t*)(Ch + (size_t)m * N + n)       = hpk2(v0, v1);
                *(uint32_t*)(Ch + (size_t)(m + 8) * N + n) = hpk2(v2, v3);
            }
        }
    }
}

// ==================== flash attention (fp16, 64-key tiles, 4-stage, race-free) ====================
// Mask folded in: tok ints staged via cp.async, compared at use.
#define FA_Q     0
#define FA_STG0  18432
#define FA_K     0
#define FA_V     9216
#define FA_MSK   18432
#define FA_STGSZ 18688
#define FA_SMEM  (18432 + 4 * 18688)   // 93184

__global__ __launch_bounds__(256, 2) void flash_attn(
    const __half* __restrict__ qkv, const int* __restrict__ tok,
    __half* __restrict__ ch)
{
    extern __shared__ __align__(128) char smem_raw[];
    const uint32_t base = smem_to_u32(smem_raw);
    const uint32_t sQ = base + FA_Q;

    const int tid = threadIdx.x, lane = tid & 31, wid = tid >> 5;
    const int q0 = blockIdx.x * 128;
    const int z = blockIdx.y, b = z >> 4, h = z & 15;
    const uint32_t lrow = lane & 15, khalf = lane >> 4;
    const int cpos = (lane & 3) * 2;
    const int colQ = h * 64, colK = 1024 + h * 64, colV = 2048 + h * 64;

    #pragma unroll
    for (int i = 0; i < 2; i++) {
        int idx = tid + i * 256;
        int row = idx >> 2, seg2 = (idx & 3) * 2;
        size_t src = (size_t)(b * SS + q0 + row) * NQKV + colQ + seg2 * 8;
        CP_ASYNC16(sQ + row * 144 + seg2 * 16, qkv + src);
        CP_ASYNC16(sQ + row * 144 + seg2 * 16 + 16, qkv + src + 8);
    }
    CP_COMMIT();

    #define FA_FILL(kt_) do { \
        const int stg_ = (kt_) & 3; \
        const uint32_t sb_ = base + FA_STG0 + stg_ * FA_STGSZ; \
        const int k0_ = (kt_) * 64; \
        { int row_ = tid >> 2, s2_ = tid & 3; \
          size_t srck_ = (size_t)(b * SS + k0_ + row_) * NQKV + colK + s2_ * 16; \
          uint32_t dstk_ = sb_ + FA_K + row_ * 144 + s2_ * 32; \
          CP_ASYNC16(dstk_, qkv + srck_); \
          CP_ASYNC16(dstk_ + 16, qkv + srck_ + 8); \
          size_t srcv_ = (size_t)(b * SS + k0_ + row_) * NQKV + colV + s2_ * 16; \
          uint32_t dstv_ = sb_ + FA_V + row_ * 144 + s2_ * 32; \
          CP_ASYNC16(dstv_, qkv + srcv_); \
          CP_ASYNC16(dstv_ + 16, qkv + srcv_ + 8); } \
        if (tid < 16) \
            CP_ASYNC16(sb_ + FA_MSK + tid * 16, tok + b * SS + k0_ + tid * 4); \
        CP_COMMIT(); \
    } while (0)

    FA_FILL(0);
    FA_FILL(1);

    // hoisted Q fragments: wait only the Q group (2 newer groups pending)
    uint32_t qf[4][4];
    CP_WAITG(2);
    __syncthreads();
    #pragma unroll
    for (int ks = 0; ks < 4; ks++) {
        uint32_t ad = (wid * 16 + lrow) * 144 + (ks * 16 + khalf * 8) * 2;
        LDM_X4(qf[ks][0], qf[ks][1], qf[ks][2], qf[ks][3], sQ + ad);
    }

    float m0 = -3.0e38f, m1 = -3.0e38f, l0 = 0.f, l1 = 0.f;
    float O[8][4];
    #pragma unroll
    for (int i = 0; i < 8; i++)
        #pragma unroll
        for (int j = 0; j < 4; j++) O[i][j] = 0.f;

    for (int kt = 0; kt < 16; kt++) {
        if (kt + 2 < 16) { FA_FILL(kt + 2); CP_WAITG(2); }
        else if (kt + 1 < 16) CP_WAITG(1);
        else CP_WAITG(0);
        __syncthreads();

        const uint32_t sb = base + FA_STG0 + (uint32_t)(kt & 3) * FA_STGSZ;
        const uint32_t sK = sb + FA_K, sV = sb + FA_V;
        const int* toki = (const int*)(smem_raw + FA_STG0 + (kt & 3) * FA_STGSZ + FA_MSK);

        float Sv[8][4];
        #pragma unroll
        for (int i = 0; i < 8; i++)
            #pragma unroll
            for (int j = 0; j < 4; j++) Sv[i][j] = 0.f;

        #pragma unroll
        for (int ks = 0; ks < 4; ks++) {
            #pragma unroll
            for (int ng = 0; ng < 4; ng++) {
                uint32_t bd = (ng * 16 + lrow) * 144 + (ks * 16 + khalf * 8) * 2;
                uint32_t bh_[4];
                LDM_X4(bh_[0], bh_[1], bh_[2], bh_[3], sK + bd);
                MMA_F16(Sv[2 * ng],     qf[ks], bh_[0], bh_[2]);
                MMA_F16(Sv[2 * ng + 1], qf[ks], bh_[1], bh_[3]);
            }
        }

        float mt0 = -3.0e38f, mt1 = -3.0e38f;
        #pragma unroll
        for (int nb = 0; nb < 8; nb++) {
            float mk0 = (toki[nb * 8 + cpos]     == 0) ? -1e9f : 0.f;
            float mk1 = (toki[nb * 8 + cpos + 1] == 0) ? -1e9f : 0.f;
            Sv[nb][0] = Sv[nb][0] * 0.125f + mk0;
            Sv[nb][1] = Sv[nb][1] * 0.125f + mk1;
            Sv[nb][2] = Sv[nb][2] * 0.125f + mk0;
            Sv[nb][3] = Sv[nb][3] * 0.125f + mk1;
            mt0 = fmaxf(mt0, fmaxf(Sv[nb][0], Sv[nb][1]));
            mt1 = fmaxf(mt1, fmaxf(Sv[nb][2], Sv[nb][3]));
        }
        mt0 = fmaxf(mt0, __shfl_xor_sync(0xffffffffu, mt0, 1));
        mt0 = fmaxf(mt0, __shfl_xor_sync(0xffffffffu, mt0, 2));
        mt1 = fmaxf(mt1, __shfl_xor_sync(0xffffffffu, mt1, 1));
        mt1 = fmaxf(mt1, __shfl_xor_sync(0xffffffffu, mt1, 2));

        float mn0 = fmaxf(m0, mt0), mn1 = fmaxf(m1, mt1);
        float al0 = __expf(m0 - mn0), al1 = __expf(m1 - mn1);
        float su0 = 0.f, su1 = 0.f;
        #pragma unroll
        for (int nb = 0; nb < 8; nb++) {
            Sv[nb][0] = __expf(Sv[nb][0] - mn0);
            Sv[nb][1] = __expf(Sv[nb][1] - mn0);
            Sv[nb][2] = __expf(Sv[nb][2] - mn1);
            Sv[nb][3] = __expf(Sv[nb][3] - mn1);
            su0 += Sv[nb][0] + Sv[nb][1];
            su1 += Sv[nb][2] + Sv[nb][3];
        }
        su0 += __shfl_xor_sync(0xffffffffu, su0, 1);
        su0 += __shfl_xor_sync(0xffffffffu, su0, 2);
        su1 += __shfl_xor_sync(0xffffffffu, su1, 1);
        su1 += __shfl_xor_sync(0xffffffffu, su1, 2);

        l0 = l0 * al0 + su0;
        l1 = l1 * al1 + su1;
        m0 = mn0; m1 = mn1;
        #pragma unroll
        for (int nf = 0; nf < 8; nf++) {
            O[nf][0] *= al0; O[nf][1] *= al0;
            O[nf][2] *= al1; O[nf][3] *= al1;
        }

        #pragma unroll
        for (int j = 0; j < 4; j++) {
            uint32_t pa[4];
            pa[0] = hpk2(Sv[2*j][0],   Sv[2*j][1]);
            pa[1] = hpk2(Sv[2*j][2],   Sv[2*j][3]);
            pa[2] = hpk2(Sv[2*j+1][0], Sv[2*j+1][1]);
            pa[3] = hpk2(Sv[2*j+1][2], Sv[2*j+1][3]);
            #pragma unroll
            for (int ng = 0; ng < 4; ng++) {
                uint32_t bd = sV + (j * 16 + lrow) * 144 + (ng * 16 + khalf * 8) * 2;
                uint32_t v0, v1, v2, v3;
                LDM_X4_T(v0, v1, v2, v3, bd);
                MMA_F16(O[2 * ng],     pa, v0, v1);
                MMA_F16(O[2 * ng + 1], pa, v2, v3);
            }
        }
    }
    #undef FA_FILL

    float i0 = 1.f / l0, i1 = 1.f / l1;
    const int rgl = b * SS + q0 + wid * 16 + (lane >> 2);
    #pragma unroll
    for (int nf = 0; nf < 8; nf++) {
        int col = h * 64 + nf * 8 + cpos;
        size_t o0 = (size_t)rgl * HDD + col;
        size_t o1 = (size_t)(rgl + 8) * HDD + col;
        *(uint32_t*)(ch + o0) = hpk2(O[nf][0] * i0, O[nf][1] * i0);
        *(uint32_t*)(ch + o1) = hpk2(O[nf][2] * i1, O[nf][3] * i1);
    }
}

// ==================== embed + add_ln ====================
__global__ __launch_bounds__(256) void embed_kernel(
    const int* __restrict__ tok, const float* __restrict__ emb,
    float* __restrict__ x, __half* __restrict__ xh)
{
    int row = blockIdx.x;
    int s = row % SS;
    int t = tok[row];
    const float* e = emb + (size_t)t * DD;
    for (int d = threadIdx.x; d < DD; d += 256) {
        int i = d >> 1;
        float freq = expf(-((float)(2 * i) / (float)DD) * 9.210340371976184f);
        float a = (float)s * freq;
        float pe = (d & 1) ? cosf(a) : sinf(a);
        float v = e[d] + pe;
        size_t o = (size_t)row * DD + d;
        x[o] = v;
        xh[o] = __float2half_rn(v);
    }
}

__device__ __forceinline__ float block_sum(float v, float* sh) {
    __syncthreads();
    #pragma unroll
    for (int o = 16; o > 0; o >>= 1) v += __shfl_xor_sync(0xffffffffu, v, o);
    int w = threadIdx.x >> 5;
    if ((threadIdx.x & 31) == 0) sh[w] = v;
    __syncthreads();
    float t = (threadIdx.x < 8) ? sh[threadIdx.x] : 0.0f;
    #pragma unroll
    for (int o = 4; o > 0; o >>= 1) t += __shfl_xor_sync(0xffffffffu, t, o);
    if (threadIdx.x == 0) sh[0] = t;
    __syncthreads();
    return sh[0];
}

__global__ __launch_bounds__(256) void add_ln(
    const float* __restrict__ xin, const float* __restrict__ delta,
    const float* __restrict__ g, const float* __restrict__ bta,
    float* __restrict__ out, __half* __restrict__ oh)
{
    size_t row = blockIdx.x;
    const float* xr = xin   + row * DD;
    const float* dr = delta + row * DD;
    int tid = threadIdx.x;
    __shared__ float red[8];

    float v[4];
    float s = 0.f;
    #pragma unroll
    for (int j = 0; j < 4; j++) {
        int c = tid + j * 256;
        v[j] = xr[c] + dr[c];
        s += v[j];
    }
    s = block_sum(s, red);
    float mu = s * (1.0f / 1024.0f);
    float var = 0.f;
    #pragma unroll
    for (int j = 0; j < 4; j++) { float t = v[j] - mu; var += t * t; }
    var = block_sum(var, red) * (1.0f / 1024.0f);
    float inv = rsqrtf(var + 1e-5f);
    #pragma unroll
    for (int j = 0; j < 4; j++) {
        int c = tid + j * 256;
        float o = (v[j] - mu) * inv * g[c] + bta[c];
        size_t idx = row * DD + c;
        out[idx] = o;
        if (oh) oh[idx] = __float2half_rn(o);
    }
}

// ==================== host orchestration ====================
extern "C" void kernel_launch(void* const* d_in, const int* in_sizes, int n_in,
                              void* d_out, int out_size)
{
    (void)in_sizes; (void)n_in; (void)out_size;
    const int*   tok  = (const int*)  d_in[0];
    const float* emb  = (const float*)d_in[1];
    const float* Wq   = (const float*)d_in[2];
    const float* bq   = (const float*)d_in[3];
    const float* Wk   = (const float*)d_in[4];
    const float* bk   = (const float*)d_in[5];
    const float* Wv   = (const float*)d_in[6];
    const float* bv   = (const float*)d_in[7];
    const float* Wo   = (const float*)d_in[8];
    const float* bo   = (const float*)d_in[9];
    const float* ln1g = (const float*)d_in[10];
    const float* ln1b = (const float*)d_in[11];
    const float* W1   = (const float*)d_in[12];
    const float* W2   = (const float*)d_in[13];
    const float* ln2g = (const float*)d_in[14];
    const float* ln2b = (const float*)d_in[15];
    float* out = (float*)d_out;

    float *x, *tmp, *bqkv;
    __half *xh, *qkv, *ch, *fh, *wh;
    cudaGetSymbolAddress((void**)&x,     g_x);
    cudaGetSymbolAddress((void**)&tmp,   g_tmp);
    cudaGetSymbolAddress((void**)&xh,    g_xh);
    cudaGetSymbolAddress((void**)&qkv,   g_qkv);
    cudaGetSymbolAddress((void**)&ch,    g_ch);
    cudaGetSymbolAddress((void**)&fh,    g_fh);
    cudaGetSymbolAddress((void**)&wh,    g_wh);
    cudaGetSymbolAddress((void**)&bqkv,  g_bqkv);

    const int GSM128 = 3 * (128 * SPB + ARR_BB);   // 110592
    const int GSM64  = 3 * (64 * SPB + ARR_BB);    // 82944

    static int attr_done = 0;
    static cudaStream_t s2;
    static cudaEvent_t evFork, evPrep, evJoin;
    if (!attr_done) {
        cudaFuncSetAttribute(gemm_mma<128>, cudaFuncAttributeMaxDynamicSharedMemorySize, GSM128);
        cudaFuncSetAttribute(gemm_mma<64>,  cudaFuncAttributeMaxDynamicSharedMemorySize, GSM64);
        cudaFuncSetAttribute(flash_attn, cudaFuncAttributeMaxDynamicSharedMemorySize, FA_SMEM);
        cudaStreamCreateWithFlags(&s2, cudaStreamNonBlocking);
        cudaEventCreateWithFlags(&evFork, cudaEventDisableTiming);
        cudaEventCreateWithFlags(&evPrep, cudaEventDisableTiming);
        cudaEventCreateWithFlags(&evJoin, cudaEventDisableTiming);
        attr_done = 1;
    }

    // fork immediately: prep pipeline split across two streams
    cudaEventRecord(evFork, 0);
    cudaStreamWaitEvent(s2, evFork, 0);

    // s0: embed (needed for QKV gemm)
    embed_kernel<<<MR, 256>>>(tok, emb, x, xh);

    // s2: biascat + tsplit_qkv (needed for QKV gemm), then Wo/W1/W2
    biascat_kernel<<<LL * NQKV / 256, 256, 0, s2>>>(bq, bk, bv, bqkv);
    tsplit_qkv<<<dim3(HDD/64, DD/64, LL*3), 256, 0, s2>>>(Wq, Wk, Wv, wh + WQKV_OFF);
    cudaEventRecord(evPrep, s2);
    tsplit_b<<<dim3(DD/64, HDD/64, LL), 256, 0, s2>>>(Wo, wh + WOT_OFF, HDD, DD);
    tsplit_b<<<dim3(FF/64, DD/64, LL), 256, 0, s2>>>(W1, wh + W1T_OFF, DD, FF);
    tsplit_b<<<dim3(DD/64, FF/64, LL), 256, 0, s2>>>(W2, wh + W2T_OFF, FF, DD);
    cudaEventRecord(evJoin, s2);

    cudaStreamWaitEvent(0, evPrep, 0);

    dim3 gQKV(NQKV/128, MR/128);   // MT=128
    dim3 gWo(DD/128, MR/64);       // MT=64
    dim3 gF1(FF/128, MR/128);      // MT=128
    dim3 gF2(DD/128, MR/64);       // MT=64
    dim3 gFA(SS/128, BB*HH);

    for (int l = 0; l < LL; l++) {
        const __half* wqkv = wh + WQKV_OFF + (size_t)l * 3 * SZ_P;
        const __half* woh  = wh + WOT_OFF + (size_t)l * SZ_P;
        const __half* w1h  = wh + W1T_OFF + (size_t)l * SZ_F;
        const __half* w2h  = wh + W2T_OFF + (size_t)l * SZ_F;

        gemm_mma<128><<<gQKV, 256, GSM128>>>(xh, wqkv, bqkv + (size_t)l*NQKV,
                                             (float*)nullptr, qkv, DD, NQKV, 0);

        flash_attn<<<gFA, 256, FA_SMEM>>>(qkv, tok, ch);

        if (l == 0) cudaStreamWaitEvent(0, evJoin, 0);

        gemm_mma<64><<<gWo, 256, GSM64>>>(ch, woh, bo + (size_t)l*DD,
                                          tmp, (__half*)nullptr, HDD, DD, 0);
        add_ln<<<MR, 256>>>(x, tmp, ln1g + (size_t)l*DD, ln1b + (size_t)l*DD, x, xh);

        gemm_mma<128><<<gF1, 256, GSM128>>>(xh, w1h, (const float*)nullptr,
                                            (float*)nullptr, fh, DD, FF, 1);
        gemm_mma<64><<<gF2, 256, GSM64>>>(fh, w2h, (const float*)nullptr,
                                          tmp, (__half*)nullptr, FF, DD, 0);

        float* dst = (l == LL - 1) ? out : x;
        __half* dsth = (l == LL - 1) ? (__half*)nullptr : xh;
        add_ln<<<MR, 256>>>(x, tmp, ln2g + (size_t)l*DD, ln2b + (size_t)l*DD, dst, dsth);
    }
}

// round 16
// speedup vs baseline: 1.1042x; 1.0041x over previous
#include <cuda_runtime.h>
#include <cuda_fp16.h>
#include <math.h>
#include <stdint.h>

#define BB   2
#define SS   1024
#define DD   1024
#define HH   16
#define HDD  1024
#define FF   4096
#define LL   4
#define MR   (BB*SS)
#define NQKV 3072

// -------------------- scratch --------------------
__device__ float g_x  [MR * DD];
__device__ float g_tmp[MR * DD];
__device__ __half g_xh[MR * DD];
__device__ __half g_qkv[(size_t)MR * NQKV];
__device__ __half g_ch[MR * HDD];
__device__ __half g_fh[(size_t)MR * FF];
__device__ float g_bqkv[LL * NQKV];

#define SZ_P ((size_t)HDD * DD)
#define SZ_F ((size_t)DD * FF)
#define WQKV_OFF ((size_t)0)
#define WOT_OFF  ((size_t)LL * 3 * SZ_P)
#define W1T_OFF  (WOT_OFF + (size_t)LL * SZ_P)
#define W2T_OFF  (W1T_OFF + (size_t)LL * SZ_F)
#define WT_TOTAL (W2T_OFF + (size_t)LL * SZ_F)
__device__ __half g_wh[WT_TOTAL];

// ==================== helpers ====================
__device__ __forceinline__ uint32_t smem_to_u32(const void* p) {
    uint32_t a;
    asm("{ .reg .u64 t; cvta.to.shared.u64 t, %1; cvt.u32.u64 %0, t; }" : "=r"(a) : "l"(p));
    return a;
}
#define CP_ASYNC16(dst, src) \
    asm volatile("cp.async.cg.shared.global [%0], [%1], 16;" \
        :: "r"((uint32_t)(dst)), "l"(__cvta_generic_to_global(src)) : "memory")
#define CP_COMMIT() asm volatile("cp.async.commit_group;" ::: "memory")
#define CP_WAITG(n) asm volatile("cp.async.wait_group %0;" :: "n"(n) : "memory")
#define LDM_X4(r0, r1, r2, r3, addr) \
    asm volatile("ldmatrix.sync.aligned.m8n8.x4.shared.b16 {%0,%1,%2,%3}, [%4];" \
        : "=r"(r0), "=r"(r1), "=r"(r2), "=r"(r3) : "r"(addr))
#define LDM_X4_T(r0, r1, r2, r3, addr) \
    asm volatile("ldmatrix.sync.aligned.m8n8.x4.trans.shared.b16 {%0,%1,%2,%3}, [%4];" \
        : "=r"(r0), "=r"(r1), "=r"(r2), "=r"(r3) : "r"(addr))
#define MMA_F16(acc, a, b0, b1) \
    asm volatile("mma.sync.aligned.m16n8k16.row.col.f32.f16.f16.f32 " \
        "{%0,%1,%2,%3},{%4,%5,%6,%7},{%8,%9},{%0,%1,%2,%3};" \
        : "+f"((acc)[0]), "+f"((acc)[1]), "+f"((acc)[2]), "+f"((acc)[3]) \
        : "r"((a)[0]), "r"((a)[1]), "r"((a)[2]), "r"((a)[3]), "r"(b0), "r"(b1))

__device__ __forceinline__ uint32_t hpk2(float a, float b) {
    __half2 t = __floats2half2_rn(a, b);
    return *reinterpret_cast<uint32_t*>(&t);
}
__device__ __forceinline__ float gelu_f(float v) {
    float x = v * 0.70710678118654752f;
    float ax = fabsf(x);
    float t = __fdividef(1.0f, fmaf(0.3275911f, ax, 1.0f));
    float p = t * fmaf(t, fmaf(t, fmaf(t, fmaf(t, 1.061405429f, -1.453152027f),
                               1.421413741f), -0.284496736f), 0.254829592f);
    float erfv = 1.0f - p * __expf(-ax * ax);
    erfv = copysignf(erfv, x);
    return 0.5f * v * (1.0f + erfv);
}

// ==================== batched weight transpose ====================
__device__ __forceinline__ void tsplit_body(
    const float* __restrict__ W, __half* __restrict__ th, int K, int N)
{
    __shared__ float ts[64][65];
    const int n0 = blockIdx.x * 64, k0 = blockIdx.y * 64;
    const int tid = threadIdx.x;
    #pragma unroll
    for (int i = 0; i < 4; i++) {
        int e = tid + i * 256;
        int r = e >> 4, c4 = (e & 15) * 4;
        float4 v = *(const float4*)&W[(size_t)(k0 + r) * N + n0 + c4];
        ts[r][c4]     = v.x; ts[r][c4 + 1] = v.y;
        ts[r][c4 + 2] = v.z; ts[r][c4 + 3] = v.w;
    }
    __syncthreads();
    const int w = tid >> 5, lane = tid & 31;
    #pragma unroll
    for (int rr = 0; rr < 8; rr++) {
        int n = w * 8 + rr;
        float a = ts[lane * 2][n], b = ts[lane * 2 + 1][n];
        size_t o = (size_t)(n0 + n) * K + k0 + lane * 2;
        *(uint32_t*)&th[o] = hpk2(a, b);
    }
}

__global__ __launch_bounds__(256) void tsplit_qkv(
    const float* __restrict__ Wq, const float* __restrict__ Wk,
    const float* __restrict__ Wv, __half* __restrict__ th)
{
    int z = blockIdx.z;
    int l = z / 3, j = z - l * 3;
    const float* W = ((j == 0) ? Wq : (j == 1) ? Wk : Wv) + (size_t)l * SZ_P;
    __half* dst = th + ((size_t)l * 3 + j) * SZ_P;
    tsplit_body(W, dst, DD, HDD);
}

__global__ __launch_bounds__(256) void tsplit_b(
    const float* __restrict__ W, __half* __restrict__ th, int K, int N)
{
    size_t off = (size_t)blockIdx.z * K * N;
    tsplit_body(W + off, th + off, K, N);
}

__global__ void biascat_kernel(const float* __restrict__ bq, const float* __restrict__ bk,
                               const float* __restrict__ bv, float* __restrict__ o)
{
    int i = blockIdx.x * 256 + threadIdx.x;
    int l = i / NQKV, r = i % NQKV;
    int seg = r >> 10, n = r & 1023;
    const float* s = (seg == 0) ? bq : (seg == 1) ? bk : bv;
    o[i] = s[l * 1024 + n];
}

// ==================== fp16 HMMA GEMM, KC=64, 3-slot d=1 pipeline (d<=S-2) ====================
#define KCB 64
#define SPB 144
#define ARR_BB (128 * SPB)

template<int MT>
__global__ __launch_bounds__(256, 2) void gemm_mma(
    const __half* __restrict__ A, const __half* __restrict__ B,
    const float* __restrict__ bias, float* __restrict__ C,
    __half* __restrict__ Ch, int K, int N, int act)
{
    constexpr uint32_t ARR_A = (uint32_t)MT * SPB;
    constexpr uint32_t STGB  = ARR_A + ARR_BB;
    constexpr int AIT  = MT / 32;
    constexpr int NFRAG = (MT == 128) ? 8 : 4;
    constexpr int NB    = NFRAG / 2;
    constexpr int WNW   = (MT == 128) ? 64 : 32;

    extern __shared__ __align__(128) char smem_raw[];
    const uint32_t sbase = smem_to_u32(smem_raw);

    const int tid  = threadIdx.x;
    const int lane = tid & 31;
    const int wid  = tid >> 5;
    const int wm   = (MT == 128) ? (wid & 3) : (wid & 1);
    const int wn   = (MT == 128) ? (wid >> 2) : (wid >> 1);
    const int m0 = blockIdx.y * MT, n0 = blockIdx.x * 128;

    float acc[2][NFRAG][4];
    #pragma unroll
    for (int i = 0; i < 2; i++)
        #pragma unroll
        for (int j = 0; j < NFRAG; j++)
            #pragma unroll
            for (int q2 = 0; q2 < 4; q2++) acc[i][j][q2] = 0.f;

    const int nc = K >> 6;

    #define FILL_STAGE(stg, kk) do { \
        const uint32_t so_ = sbase + (uint32_t)(stg) * STGB; \
        _Pragma("unroll") \
        for (int i_ = 0; i_ < AIT + 4; i_++) { \
            const int isA_ = (i_ < AIT); \
            int rem_ = (isA_ ? i_ : (i_ - AIT)) * 256 + tid; \
            int row_ = rem_ >> 3, seg_ = rem_ & 7; \
            const __half* p_ = isA_ ? A : B; \
            int rb_ = isA_ ? m0 : n0; \
            uint32_t dst_ = so_ + (isA_ ? 0u : ARR_A) + row_ * SPB + seg_ * 16; \
            CP_ASYNC16(dst_, p_ + (size_t)(rb_ + row_) * K + (kk) + seg_ * 8); \
        } \
        CP_COMMIT(); \
    } while (0)

    FILL_STAGE(0, 0);

    const uint32_t lrow  = lane & 15;
    const uint32_t khalf = lane >> 4;
    const uint32_t a_row_off = (wm * 32 + lrow) * SPB;
    const uint32_t b_row_off = (wn * WNW + lrow) * SPB;

    int slot = 0, fslot = 1;
    for (int c = 0; c < nc; c++) {
        if (c + 1 < nc) {
            FILL_STAGE(fslot, (c + 1) * KCB);
            fslot = (fslot == 2) ? 0 : fslot + 1;
            CP_WAITG(1);
        } else {
            CP_WAITG(0);
        }
        __syncthreads();

        const uint32_t so = sbase + (uint32_t)slot * STGB;
        slot = (slot == 2) ? 0 : slot + 1;
        const uint32_t sA = so, sB = so + ARR_A;

        #pragma unroll
        for (int ks = 0; ks < 4; ks++) {
            const uint32_t kofs = ks * 32 + khalf * 16;
            uint32_t af[2][4];
            #pragma unroll
            for (int mb = 0; mb < 2; mb++) {
                uint32_t ad = a_row_off + mb * 16 * SPB + kofs;
                LDM_X4(af[mb][0], af[mb][1], af[mb][2], af[mb][3], sA + ad);
            }
            #pragma unroll
            for (int nb = 0; nb < NB; nb++) {
                uint32_t bd = b_row_off + nb * 16 * SPB + kofs;
                uint32_t bf_[4];
                LDM_X4(bf_[0], bf_[1], bf_[2], bf_[3], sB + bd);
                #pragma unroll
                for (int mb = 0; mb < 2; mb++) {
                    MMA_F16(acc[mb][nb * 2],     af[mb], bf_[0], bf_[2]);
                    MMA_F16(acc[mb][nb * 2 + 1], af[mb], bf_[1], bf_[3]);
                }
            }
        }
    }
    #undef FILL_STAGE

    const int mrow = m0 + wm * 32 + (lane >> 2);
    const int ncol0 = n0 + wn * WNW + (lane & 3) * 2;
    #pragma unroll
    for (int mb = 0; mb < 2; mb++) {
        #pragma unroll
        for (int nf = 0; nf < NFRAG; nf++) {
            int n = ncol0 + nf * 8;
            float b0v = bias ? bias[n]     : 0.f;
            float b1v = bias ? bias[n + 1] : 0.f;
            float v0 = acc[mb][nf][0] + b0v;
            float v1 = acc[mb][nf][1] + b1v;
            float v2 = acc[mb][nf][2] + b0v;
            float v3 = acc[mb][nf][3] + b1v;
            if (act) { v0 = gelu_f(v0); v1 = gelu_f(v1); v2 = gelu_f(v2); v3 = gelu_f(v3); }
            int m = mrow + mb * 16;
            if (C) {
                *(float2*)(C + (size_t)m * N + n)       = make_float2(v0, v1);
                *(float2*)(C + (size_t)(m + 8) * N + n) = make_float2(v2, v3);
            }
            if (Ch) {
                *(uint32_t*)(Ch + (size_t)m * N + n)       = hpk2(v0, v1);
                *(uint32_t*)(Ch + (size_t)(m + 8) * N + n) = hpk2(v2, v3);
            }
        }
    }
}

// ==================== flash attention (fp16, 64-key tiles, 4-stage, race-free) ====================
#define FA_Q     0
#define FA_STG0  18432
#define FA_K     0
#define FA_V     9216
#define FA_MSK   18432
#define FA_STGSZ 18688
#define FA_SMEM  (18432 + 4 * 18688)   // 93184

__global__ __launch_bounds__(256, 2) void flash_attn(
    const __half* __restrict__ qkv, const int* __restrict__ tok,
    __half* __restrict__ ch)
{
    extern __shared__ __align__(128) char smem_raw[];
    const uint32_t base = smem_to_u32(smem_raw);
    const uint32_t sQ = base + FA_Q;

    const int tid = threadIdx.x, lane = tid & 31, wid = tid >> 5;
    const int q0 = blockIdx.x * 128;
    const int z = blockIdx.y, b = z >> 4, h = z & 15;
    const uint32_t lrow = lane & 15, khalf = lane >> 4;
    const int cpos = (lane & 3) * 2;
    const int colQ = h * 64, colK = 1024 + h * 64, colV = 2048 + h * 64;

    #pragma unroll
    for (int i = 0; i < 2; i++) {
        int idx = tid + i * 256;
        int row = idx >> 2, seg2 = (idx & 3) * 2;
        size_t src = (size_t)(b * SS + q0 + row) * NQKV + colQ + seg2 * 8;
        CP_ASYNC16(sQ + row * 144 + seg2 * 16, qkv + src);
        CP_ASYNC16(sQ + row * 144 + seg2 * 16 + 16, qkv + src + 8);
    }
    CP_COMMIT();

    #define FA_FILL(kt_) do { \
        const int stg_ = (kt_) & 3; \
        const uint32_t sb_ = base + FA_STG0 + stg_ * FA_STGSZ; \
        const int k0_ = (kt_) * 64; \
        { int row_ = tid >> 2, s2_ = tid & 3; \
          size_t srck_ = (size_t)(b * SS + k0_ + row_) * NQKV + colK + s2_ * 16; \
          uint32_t dstk_ = sb_ + FA_K + row_ * 144 + s2_ * 32; \
          CP_ASYNC16(dstk_, qkv + srck_); \
          CP_ASYNC16(dstk_ + 16, qkv + srck_ + 8); \
          size_t srcv_ = (size_t)(b * SS + k0_ + row_) * NQKV + colV + s2_ * 16; \
          uint32_t dstv_ = sb_ + FA_V + row_ * 144 + s2_ * 32; \
          CP_ASYNC16(dstv_, qkv + srcv_); \
          CP_ASYNC16(dstv_ + 16, qkv + srcv_ + 8); } \
        if (tid < 16) \
            CP_ASYNC16(sb_ + FA_MSK + tid * 16, tok + b * SS + k0_ + tid * 4); \
        CP_COMMIT(); \
    } while (0)

    FA_FILL(0);
    FA_FILL(1);

    uint32_t qf[4][4];
    CP_WAITG(2);
    __syncthreads();
    #pragma unroll
    for (int ks = 0; ks < 4; ks++) {
        uint32_t ad = (wid * 16 + lrow) * 144 + (ks * 16 + khalf * 8) * 2;
        LDM_X4(qf[ks][0], qf[ks][1], qf[ks][2], qf[ks][3], sQ + ad);
    }

    float m0 = -3.0e38f, m1 = -3.0e38f, l0 = 0.f, l1 = 0.f;
    float O[8][4];
    #pragma unroll
    for (int i = 0; i < 8; i++)
        #pragma unroll
        for (int j = 0; j < 4; j++) O[i][j] = 0.f;

    for (int kt = 0; kt < 16; kt++) {
        if (kt + 2 < 16) { FA_FILL(kt + 2); CP_WAITG(2); }
        else if (kt + 1 < 16) CP_WAITG(1);
        else CP_WAITG(0);
        __syncthreads();

        const uint32_t sb = base + FA_STG0 + (uint32_t)(kt & 3) * FA_STGSZ;
        const uint32_t sK = sb + FA_K, sV = sb + FA_V;
        const int* toki = (const int*)(smem_raw + FA_STG0 + (kt & 3) * FA_STGSZ + FA_MSK);

        float Sv[8][4];
        #pragma unroll
        for (int i = 0; i < 8; i++)
            #pragma unroll
            for (int j = 0; j < 4; j++) Sv[i][j] = 0.f;

        #pragma unroll
        for (int ks = 0; ks < 4; ks++) {
            #pragma unroll
            for (int ng = 0; ng < 4; ng++) {
                uint32_t bd = (ng * 16 + lrow) * 144 + (ks * 16 + khalf * 8) * 2;
                uint32_t bh_[4];
                LDM_X4(bh_[0], bh_[1], bh_[2], bh_[3], sK + bd);
                MMA_F16(Sv[2 * ng],     qf[ks], bh_[0], bh_[2]);
                MMA_F16(Sv[2 * ng + 1], qf[ks], bh_[1], bh_[3]);
            }
        }

        float mt0 = -3.0e38f, mt1 = -3.0e38f;
        #pragma unroll
        for (int nb = 0; nb < 8; nb++) {
            float mk0 = (toki[nb * 8 + cpos]     == 0) ? -1e9f : 0.f;
            float mk1 = (toki[nb * 8 + cpos + 1] == 0) ? -1e9f : 0.f;
            Sv[nb][0] = Sv[nb][0] * 0.125f + mk0;
            Sv[nb][1] = Sv[nb][1] * 0.125f + mk1;
            Sv[nb][2] = Sv[nb][2] * 0.125f + mk0;
            Sv[nb][3] = Sv[nb][3] * 0.125f + mk1;
            mt0 = fmaxf(mt0, fmaxf(Sv[nb][0], Sv[nb][1]));
            mt1 = fmaxf(mt1, fmaxf(Sv[nb][2], Sv[nb][3]));
        }
        mt0 = fmaxf(mt0, __shfl_xor_sync(0xffffffffu, mt0, 1));
        mt0 = fmaxf(mt0, __shfl_xor_sync(0xffffffffu, mt0, 2));
        mt1 = fmaxf(mt1, __shfl_xor_sync(0xffffffffu, mt1, 1));
        mt1 = fmaxf(mt1, __shfl_xor_sync(0xffffffffu, mt1, 2));

        float mn0 = fmaxf(m0, mt0), mn1 = fmaxf(m1, mt1);
        float al0 = __expf(m0 - mn0), al1 = __expf(m1 - mn1);
        float su0 = 0.f, su1 = 0.f;
        #pragma unroll
        for (int nb = 0; nb < 8; nb++) {
            Sv[nb][0] = __expf(Sv[nb][0] - mn0);
            Sv[nb][1] = __expf(Sv[nb][1] - mn0);
            Sv[nb][2] = __expf(Sv[nb][2] - mn1);
            Sv[nb][3] = __expf(Sv[nb][3] - mn1);
            su0 += Sv[nb][0] + Sv[nb][1];
            su1 += Sv[nb][2] + Sv[nb][3];
        }
        su0 += __shfl_xor_sync(0xffffffffu, su0, 1);
        su0 += __shfl_xor_sync(0xffffffffu, su0, 2);
        su1 += __shfl_xor_sync(0xffffffffu, su1, 1);
        su1 += __shfl_xor_sync(0xffffffffu, su1, 2);

        l0 = l0 * al0 + su0;
        l1 = l1 * al1 + su1;
        m0 = mn0; m1 = mn1;
        #pragma unroll
        for (int nf = 0; nf < 8; nf++) {
            O[nf][0] *= al0; O[nf][1] *= al0;
            O[nf][2] *= al1; O[nf][3] *= al1;
        }

        #pragma unroll
        for (int j = 0; j < 4; j++) {
            uint32_t pa[4];
            pa[0] = hpk2(Sv[2*j][0],   Sv[2*j][1]);
            pa[1] = hpk2(Sv[2*j][2],   Sv[2*j][3]);
            pa[2] = hpk2(Sv[2*j+1][0], Sv[2*j+1][1]);
            pa[3] = hpk2(Sv[2*j+1][2], Sv[2*j+1][3]);
            #pragma unroll
            for (int ng = 0; ng < 4; ng++) {
                uint32_t bd = sV + (j * 16 + lrow) * 144 + (ng * 16 + khalf * 8) * 2;
                uint32_t v0, v1, v2, v3;
                LDM_X4_T(v0, v1, v2, v3, bd);
                MMA_F16(O[2 * ng],     pa, v0, v1);
                MMA_F16(O[2 * ng + 1], pa, v2, v3);
            }
        }
    }
    #undef FA_FILL

    float i0 = 1.f / l0, i1 = 1.f / l1;
    const int rgl = b * SS + q0 + wid * 16 + (lane >> 2);
    #pragma unroll
    for (int nf = 0; nf < 8; nf++) {
        int col = h * 64 + nf * 8 + cpos;
        size_t o0 = (size_t)rgl * HDD + col;
        size_t o1 = (size_t)(rgl + 8) * HDD + col;
        *(uint32_t*)(ch + o0) = hpk2(O[nf][0] * i0, O[nf][1] * i0);
        *(uint32_t*)(ch + o1) = hpk2(O[nf][2] * i1, O[nf][3] * i1);
    }
}

// ==================== embed + add_ln (vectorized) ====================
__global__ __launch_bounds__(256) void embed_kernel(
    const int* __restrict__ tok, const float* __restrict__ emb,
    float* __restrict__ x, __half* __restrict__ xh)
{
    int row = blockIdx.x;
    int s = row % SS;
    int t = tok[row];
    const float* e = emb + (size_t)t * DD;
    int d = threadIdx.x * 4;                 // 4 consecutive cols/thread
    float4 ev = *(const float4*)&e[d];
    float pv[4];
    #pragma unroll
    for (int j = 0; j < 4; j++) {
        int dd = d + j;
        int i = dd >> 1;
        float freq = __expf(-((float)(2 * i) / (float)DD) * 9.210340371976184f);
        float a = (float)s * freq;
        pv[j] = (dd & 1) ? cosf(a) : sinf(a);
    }
    float4 v = make_float4(ev.x + pv[0], ev.y + pv[1], ev.z + pv[2], ev.w + pv[3]);
    size_t o = (size_t)row * DD + d;
    *(float4*)&x[o] = v;
    *(uint32_t*)&xh[o]     = hpk2(v.x, v.y);
    *(uint32_t*)&xh[o + 2] = hpk2(v.z, v.w);
}

__device__ __forceinline__ float block_sum(float v, float* sh) {
    __syncthreads();
    #pragma unroll
    for (int o = 16; o > 0; o >>= 1) v += __shfl_xor_sync(0xffffffffu, v, o);
    int w = threadIdx.x >> 5;
    if ((threadIdx.x & 31) == 0) sh[w] = v;
    __syncthreads();
    float t = (threadIdx.x < 8) ? sh[threadIdx.x] : 0.0f;
    #pragma unroll
    for (int o = 4; o > 0; o >>= 1) t += __shfl_xor_sync(0xffffffffu, t, o);
    if (threadIdx.x == 0) sh[0] = t;
    __syncthreads();
    return sh[0];
}

__global__ __launch_bounds__(256) void add_ln(
    const float* __restrict__ xin, const float* __restrict__ delta,
    const float* __restrict__ g, const float* __restrict__ bta,
    float* __restrict__ out, __half* __restrict__ oh)
{
    size_t row = blockIdx.x;
    const float* xr = xin   + row * DD;
    const float* dr = delta + row * DD;
    int tid = threadIdx.x;
    __shared__ float red[8];

    int c = tid * 4;                          // 4 consecutive cols/thread
    float4 xv = *(const float4*)&xr[c];
    float4 dv = *(const float4*)&dr[c];
    float v[4] = { xv.x + dv.x, xv.y + dv.y, xv.z + dv.z, xv.w + dv.w };
    float s = (v[0] + v[1]) + (v[2] + v[3]);
    s = block_sum(s, red);
    float mu = s * (1.0f / 1024.0f);
    float var = 0.f;
    #pragma unroll
    for (int j = 0; j < 4; j++) { float t = v[j] - mu; var += t * t; }
    var = block_sum(var, red) * (1.0f / 1024.0f);
    float inv = rsqrtf(var + 1e-5f);

    float4 gv = *(const float4*)&g[c];
    float4 bv = *(const float4*)&bta[c];
    float4 ov;
    ov.x = (v[0] - mu) * inv * gv.x + bv.x;
    ov.y = (v[1] - mu) * inv * gv.y + bv.y;
    ov.z = (v[2] - mu) * inv * gv.z + bv.z;
    ov.w = (v[3] - mu) * inv * gv.w + bv.w;
    size_t idx = row * DD + c;
    *(float4*)&out[idx] = ov;
    if (oh) {
        *(uint32_t*)&oh[idx]     = hpk2(ov.x, ov.y);
        *(uint32_t*)&oh[idx + 2] = hpk2(ov.z, ov.w);
    }
}

// ==================== host orchestration ====================
extern "C" void kernel_launch(void* const* d_in, const int* in_sizes, int n_in,
                              void* d_out, int out_size)
{
    (void)in_sizes; (void)n_in; (void)out_size;
    const int*   tok  = (const int*)  d_in[0];
    const float* emb  = (const float*)d_in[1];
    const float* Wq   = (const float*)d_in[2];
    const float* bq   = (const float*)d_in[3];
    const float* Wk   = (const float*)d_in[4];
    const float* bk   = (const float*)d_in[5];
    const float* Wv   = (const float*)d_in[6];
    const float* bv   = (const float*)d_in[7];
    const float* Wo   = (const float*)d_in[8];
    const float* bo   = (const float*)d_in[9];
    const float* ln1g = (const float*)d_in[10];
    const float* ln1b = (const float*)d_in[11];
    const float* W1   = (const float*)d_in[12];
    const float* W2   = (const float*)d_in[13];
    const float* ln2g = (const float*)d_in[14];
    const float* ln2b = (const float*)d_in[15];
    float* out = (float*)d_out;

    float *x, *tmp, *bqkv;
    __half *xh, *qkv, *ch, *fh, *wh;
    cudaGetSymbolAddress((void**)&x,     g_x);
    cudaGetSymbolAddress((void**)&tmp,   g_tmp);
    cudaGetSymbolAddress((void**)&xh,    g_xh);
    cudaGetSymbolAddress((void**)&qkv,   g_qkv);
    cudaGetSymbolAddress((void**)&ch,    g_ch);
    cudaGetSymbolAddress((void**)&fh,    g_fh);
    cudaGetSymbolAddress((void**)&wh,    g_wh);
    cudaGetSymbolAddress((void**)&bqkv,  g_bqkv);

    const int GSM128 = 3 * (128 * SPB + ARR_BB);   // 110592
    const int GSM64  = 3 * (64 * SPB + ARR_BB);    // 82944

    static int attr_done = 0;
    static cudaStream_t s2;
    static cudaEvent_t evFork, evPrep, evJoin;
    if (!attr_done) {
        cudaFuncSetAttribute(gemm_mma<128>, cudaFuncAttributeMaxDynamicSharedMemorySize, GSM128);
        cudaFuncSetAttribute(gemm_mma<64>,  cudaFuncAttributeMaxDynamicSharedMemorySize, GSM64);
        cudaFuncSetAttribute(flash_attn, cudaFuncAttributeMaxDynamicSharedMemorySize, FA_SMEM);
        cudaStreamCreateWithFlags(&s2, cudaStreamNonBlocking);
        cudaEventCreateWithFlags(&evFork, cudaEventDisableTiming);
        cudaEventCreateWithFlags(&evPrep, cudaEventDisableTiming);
        cudaEventCreateWithFlags(&evJoin, cudaEventDisableTiming);
        attr_done = 1;
    }

    cudaEventRecord(evFork, 0);
    cudaStreamWaitEvent(s2, evFork, 0);

    embed_kernel<<<MR, 256>>>(tok, emb, x, xh);

    biascat_kernel<<<LL * NQKV / 256, 256, 0, s2>>>(bq, bk, bv, bqkv);
    tsplit_qkv<<<dim3(HDD/64, DD/64, LL*3), 256, 0, s2>>>(Wq, Wk, Wv, wh + WQKV_OFF);
    cudaEventRecord(evPrep, s2);
    tsplit_b<<<dim3(DD/64, HDD/64, LL), 256, 0, s2>>>(Wo, wh + WOT_OFF, HDD, DD);
    tsplit_b<<<dim3(FF/64, DD/64, LL), 256, 0, s2>>>(W1, wh + W1T_OFF, DD, FF);
    tsplit_b<<<dim3(DD/64, FF/64, LL), 256, 0, s2>>>(W2, wh + W2T_OFF, FF, DD);
    cudaEventRecord(evJoin, s2);

    cudaStreamWaitEvent(0, evPrep, 0);

    dim3 gQKV(NQKV/128, MR/128);   // MT=128
    dim3 gWo(DD/128, MR/64);       // MT=64
    dim3 gF1(FF/128, MR/128);      // MT=128
    dim3 gF2(DD/128, MR/64);       // MT=64
    dim3 gFA(SS/128, BB*HH);

    for (int l = 0; l < LL; l++) {
        const __half* wqkv = wh + WQKV_OFF + (size_t)l * 3 * SZ_P;
        const __half* woh  = wh + WOT_OFF + (size_t)l * SZ_P;
        const __half* w1h  = wh + W1T_OFF + (size_t)l * SZ_F;
        const __half* w2h  = wh + W2T_OFF + (size_t)l * SZ_F;

        gemm_mma<128><<<gQKV, 256, GSM128>>>(xh, wqkv, bqkv + (size_t)l*NQKV,
                                             (float*)nullptr, qkv, DD, NQKV, 0);

        flash_attn<<<gFA, 256, FA_SMEM>>>(qkv, tok, ch);

        if (l == 0) cudaStreamWaitEvent(0, evJoin, 0);

        gemm_mma<64><<<gWo, 256, GSM64>>>(ch, woh, bo + (size_t)l*DD,
                                          tmp, (__half*)nullptr, HDD, DD, 0);
        add_ln<<<MR, 256>>>(x, tmp, ln1g + (size_t)l*DD, ln1b + (size_t)l*DD, x, xh);

        gemm_mma<128><<<gF1, 256, GSM128>>>(xh, w1h, (const float*)nullptr,
                                            (float*)nullptr, fh, DD, FF, 1);
        gemm_mma<64><<<gF2, 256, GSM64>>>(fh, w2h, (const float*)nullptr,
                                          tmp, (__half*)nullptr, FF, DD, 0);

        float* dst = (l == LL - 1) ? out : x;
        __half* dsth = (l == LL - 1) ? (__half*)nullptr : xh;
        add_ln<<<MR, 256>>>(x, tmp, ln2g + (size_t)l*DD, ln2b + (size_t)l*DD, dst, dsth);
    }
}

// round 17
// speedup vs baseline: 1.1129x; 1.0079x over previous
#include <cuda_runtime.h>
#include <cuda_fp16.h>
#include <math.h>
#include <stdint.h>

#define BB   2
#define SS   1024
#define DD   1024
#define HH   16
#define HDD  1024
#define FF   4096
#define LL   4
#define MR   (BB*SS)
#define NQKV 3072

// -------------------- scratch --------------------
__device__ float g_x  [MR * DD];
__device__ float g_tmp[MR * DD];
__device__ __half g_xh[MR * DD];
__device__ __half g_qkv[(size_t)MR * NQKV];
__device__ __half g_ch[MR * HDD];
__device__ __half g_fh[(size_t)MR * FF];
__device__ float g_bqkv[LL * NQKV];

#define SZ_P ((size_t)HDD * DD)
#define SZ_F ((size_t)DD * FF)
#define WQKV_OFF ((size_t)0)
#define WOT_OFF  ((size_t)LL * 3 * SZ_P)
#define W1T_OFF  (WOT_OFF + (size_t)LL * SZ_P)
#define W2T_OFF  (W1T_OFF + (size_t)LL * SZ_F)
#define WT_TOTAL (W2T_OFF + (size_t)LL * SZ_F)
__device__ __half g_wh[WT_TOTAL];

// ==================== helpers ====================
__device__ __forceinline__ uint32_t smem_to_u32(const void* p) {
    uint32_t a;
    asm("{ .reg .u64 t; cvta.to.shared.u64 t, %1; cvt.u32.u64 %0, t; }" : "=r"(a) : "l"(p));
    return a;
}
#define CP_ASYNC16(dst, src) \
    asm volatile("cp.async.cg.shared.global [%0], [%1], 16;" \
        :: "r"((uint32_t)(dst)), "l"(__cvta_generic_to_global(src)) : "memory")
#define CP_COMMIT() asm volatile("cp.async.commit_group;" ::: "memory")
#define CP_WAITG(n) asm volatile("cp.async.wait_group %0;" :: "n"(n) : "memory")
#define LDM_X4(r0, r1, r2, r3, addr) \
    asm volatile("ldmatrix.sync.aligned.m8n8.x4.shared.b16 {%0,%1,%2,%3}, [%4];" \
        : "=r"(r0), "=r"(r1), "=r"(r2), "=r"(r3) : "r"(addr))
#define LDM_X4_T(r0, r1, r2, r3, addr) \
    asm volatile("ldmatrix.sync.aligned.m8n8.x4.trans.shared.b16 {%0,%1,%2,%3}, [%4];" \
        : "=r"(r0), "=r"(r1), "=r"(r2), "=r"(r3) : "r"(addr))
#define MMA_F16(acc, a, b0, b1) \
    asm volatile("mma.sync.aligned.m16n8k16.row.col.f32.f16.f16.f32 " \
        "{%0,%1,%2,%3},{%4,%5,%6,%7},{%8,%9},{%0,%1,%2,%3};" \
        : "+f"((acc)[0]), "+f"((acc)[1]), "+f"((acc)[2]), "+f"((acc)[3]) \
        : "r"((a)[0]), "r"((a)[1]), "r"((a)[2]), "r"((a)[3]), "r"(b0), "r"(b1))

__device__ __forceinline__ uint32_t hpk2(float a, float b) {
    __half2 t = __floats2half2_rn(a, b);
    return *reinterpret_cast<uint32_t*>(&t);
}
__device__ __forceinline__ float gelu_f(float v) {
    float x = v * 0.70710678118654752f;
    float ax = fabsf(x);
    float t = __fdividef(1.0f, fmaf(0.3275911f, ax, 1.0f));
    float p = t * fmaf(t, fmaf(t, fmaf(t, fmaf(t, 1.061405429f, -1.453152027f),
                               1.421413741f), -0.284496736f), 0.254829592f);
    float erfv = 1.0f - p * __expf(-ax * ax);
    erfv = copysignf(erfv, x);
    return 0.5f * v * (1.0f + erfv);
}

// ==================== batched weight transpose ====================
__device__ __forceinline__ void tsplit_body(
    const float* __restrict__ W, __half* __restrict__ th, int K, int N)
{
    __shared__ float ts[64][65];
    const int n0 = blockIdx.x * 64, k0 = blockIdx.y * 64;
    const int tid = threadIdx.x;
    #pragma unroll
    for (int i = 0; i < 4; i++) {
        int e = tid + i * 256;
        int r = e >> 4, c4 = (e & 15) * 4;
        float4 v = *(const float4*)&W[(size_t)(k0 + r) * N + n0 + c4];
        ts[r][c4]     = v.x; ts[r][c4 + 1] = v.y;
        ts[r][c4 + 2] = v.z; ts[r][c4 + 3] = v.w;
    }
    __syncthreads();
    const int w = tid >> 5, lane = tid & 31;
    #pragma unroll
    for (int rr = 0; rr < 8; rr++) {
        int n = w * 8 + rr;
        float a = ts[lane * 2][n], b = ts[lane * 2 + 1][n];
        size_t o = (size_t)(n0 + n) * K + k0 + lane * 2;
        *(uint32_t*)&th[o] = hpk2(a, b);
    }
}

__global__ __launch_bounds__(256) void tsplit_qkv(
    const float* __restrict__ Wq, const float* __restrict__ Wk,
    const float* __restrict__ Wv, __half* __restrict__ th)
{
    int z = blockIdx.z;
    int l = z / 3, j = z - l * 3;
    const float* W = ((j == 0) ? Wq : (j == 1) ? Wk : Wv) + (size_t)l * SZ_P;
    __half* dst = th + ((size_t)l * 3 + j) * SZ_P;
    tsplit_body(W, dst, DD, HDD);
}

__global__ __launch_bounds__(256) void tsplit_b(
    const float* __restrict__ W, __half* __restrict__ th, int K, int N)
{
    size_t off = (size_t)blockIdx.z * K * N;
    tsplit_body(W + off, th + off, K, N);
}

__global__ void biascat_kernel(const float* __restrict__ bq, const float* __restrict__ bk,
                               const float* __restrict__ bv, float* __restrict__ o)
{
    int i = blockIdx.x * 256 + threadIdx.x;
    int l = i / NQKV, r = i % NQKV;
    int seg = r >> 10, n = r & 1023;
    const float* s = (seg == 0) ? bq : (seg == 1) ? bk : bv;
    o[i] = s[l * 1024 + n];
}

// ==================== fp16 HMMA GEMM, KC=64, 3-slot d=1 pipeline (d<=S-2) ====================
#define KCB 64
#define SPB 144
#define ARR_BB (128 * SPB)

template<int MT>
__global__ __launch_bounds__(256, 2) void gemm_mma(
    const __half* __restrict__ A, const __half* __restrict__ B,
    const float* __restrict__ bias, float* __restrict__ C,
    __half* __restrict__ Ch, int K, int N, int act)
{
    constexpr uint32_t ARR_A = (uint32_t)MT * SPB;
    constexpr uint32_t STGB  = ARR_A + ARR_BB;
    constexpr int AIT  = MT / 32;
    constexpr int NFRAG = (MT == 128) ? 8 : 4;
    constexpr int NB    = NFRAG / 2;
    constexpr int WNW   = (MT == 128) ? 64 : 32;

    extern __shared__ __align__(128) char smem_raw[];
    const uint32_t sbase = smem_to_u32(smem_raw);

    const int tid  = threadIdx.x;
    const int lane = tid & 31;
    const int wid  = tid >> 5;
    const int wm   = (MT == 128) ? (wid & 3) : (wid & 1);
    const int wn   = (MT == 128) ? (wid >> 2) : (wid >> 1);
    const int m0 = blockIdx.y * MT, n0 = blockIdx.x * 128;

    float acc[2][NFRAG][4];
    #pragma unroll
    for (int i = 0; i < 2; i++)
        #pragma unroll
        for (int j = 0; j < NFRAG; j++)
            #pragma unroll
            for (int q2 = 0; q2 < 4; q2++) acc[i][j][q2] = 0.f;

    const int nc = K >> 6;

    #define FILL_STAGE(stg, kk) do { \
        const uint32_t so_ = sbase + (uint32_t)(stg) * STGB; \
        _Pragma("unroll") \
        for (int i_ = 0; i_ < AIT + 4; i_++) { \
            const int isA_ = (i_ < AIT); \
            int rem_ = (isA_ ? i_ : (i_ - AIT)) * 256 + tid; \
            int row_ = rem_ >> 3, seg_ = rem_ & 7; \
            const __half* p_ = isA_ ? A : B; \
            int rb_ = isA_ ? m0 : n0; \
            uint32_t dst_ = so_ + (isA_ ? 0u : ARR_A) + row_ * SPB + seg_ * 16; \
            CP_ASYNC16(dst_, p_ + (size_t)(rb_ + row_) * K + (kk) + seg_ * 8); \
        } \
        CP_COMMIT(); \
    } while (0)

    FILL_STAGE(0, 0);

    const uint32_t lrow  = lane & 15;
    const uint32_t khalf = lane >> 4;
    const uint32_t a_row_off = (wm * 32 + lrow) * SPB;
    const uint32_t b_row_off = (wn * WNW + lrow) * SPB;

    int slot = 0, fslot = 1;
    for (int c = 0; c < nc; c++) {
        if (c + 1 < nc) {
            FILL_STAGE(fslot, (c + 1) * KCB);
            fslot = (fslot == 2) ? 0 : fslot + 1;
            CP_WAITG(1);
        } else {
            CP_WAITG(0);
        }
        __syncthreads();

        const uint32_t so = sbase + (uint32_t)slot * STGB;
        slot = (slot == 2) ? 0 : slot + 1;
        const uint32_t sA = so, sB = so + ARR_A;

        #pragma unroll
        for (int ks = 0; ks < 4; ks++) {
            const uint32_t kofs = ks * 32 + khalf * 16;
            uint32_t af[2][4];
            #pragma unroll
            for (int mb = 0; mb < 2; mb++) {
                uint32_t ad = a_row_off + mb * 16 * SPB + kofs;
                LDM_X4(af[mb][0], af[mb][1], af[mb][2], af[mb][3], sA + ad);
            }
            #pragma unroll
            for (int nb = 0; nb < NB; nb++) {
                uint32_t bd = b_row_off + nb * 16 * SPB + kofs;
                uint32_t bf_[4];
                LDM_X4(bf_[0], bf_[1], bf_[2], bf_[3], sB + bd);
                #pragma unroll
                for (int mb = 0; mb < 2; mb++) {
                    MMA_F16(acc[mb][nb * 2],     af[mb], bf_[0], bf_[2]);
                    MMA_F16(acc[mb][nb * 2 + 1], af[mb], bf_[1], bf_[3]);
                }
            }
        }
    }
    #undef FILL_STAGE

    const int mrow = m0 + wm * 32 + (lane >> 2);
    const int ncol0 = n0 + wn * WNW + (lane & 3) * 2;
    #pragma unroll
    for (int mb = 0; mb < 2; mb++) {
        #pragma unroll
        for (int nf = 0; nf < NFRAG; nf++) {
            int n = ncol0 + nf * 8;
            float b0v = bias ? bias[n]     : 0.f;
            float b1v = bias ? bias[n + 1] : 0.f;
            float v0 = acc[mb][nf][0] + b0v;
            float v1 = acc[mb][nf][1] + b1v;
            float v2 = acc[mb][nf][2] + b0v;
            float v3 = acc[mb][nf][3] + b1v;
            if (act) { v0 = gelu_f(v0); v1 = gelu_f(v1); v2 = gelu_f(v2); v3 = gelu_f(v3); }
            int m = mrow + mb * 16;
            if (C) {
                *(float2*)(C + (size_t)m * N + n)       = make_float2(v0, v1);
                *(float2*)(C + (size_t)(m + 8) * N + n) = make_float2(v2, v3);
            }
            if (Ch) {
                *(uint32_t*)(Ch + (size_t)m * N + n)       = hpk2(v0, v1);
                *(uint32_t*)(Ch + (size_t)(m + 8) * N + n) = hpk2(v2, v3);
            }
        }
    }
}

// ==================== flash attention (fp16, 64-key tiles, 4-stage, race-free) ====================
#define FA_Q     0
#define FA_STG0  18432
#define FA_K     0
#define FA_V     9216
#define FA_MSK   18432
#define FA_STGSZ 18688
#define FA_SMEM  (18432 + 4 * 18688)   // 93184

__global__ __launch_bounds__(256, 2) void flash_attn(
    const __half* __restrict__ qkv, const int* __restrict__ tok,
    __half* __restrict__ ch)
{
    extern __shared__ __align__(128) char smem_raw[];
    const uint32_t base = smem_to_u32(smem_raw);
    const uint32_t sQ = base + FA_Q;

    const int tid = threadIdx.x, lane = tid & 31, wid = tid >> 5;
    const int q0 = blockIdx.x * 128;
    const int z = blockIdx.y, b = z >> 4, h = z & 15;
    const uint32_t lrow = lane & 15, khalf = lane >> 4;
    const int cpos = (lane & 3) * 2;
    const int colQ = h * 64, colK = 1024 + h * 64, colV = 2048 + h * 64;

    #pragma unroll
    for (int i = 0; i < 2; i++) {
        int idx = tid + i * 256;
        int row = idx >> 2, seg2 = (idx & 3) * 2;
        size_t src = (size_t)(b * SS + q0 + row) * NQKV + colQ + seg2 * 8;
        CP_ASYNC16(sQ + row * 144 + seg2 * 16, qkv + src);
        CP_ASYNC16(sQ + row * 144 + seg2 * 16 + 16, qkv + src + 8);
    }
    CP_COMMIT();

    #define FA_FILL(kt_) do { \
        const int stg_ = (kt_) & 3; \
        const uint32_t sb_ = base + FA_STG0 + stg_ * FA_STGSZ; \
        const int k0_ = (kt_) * 64; \
        { int row_ = tid >> 2, s2_ = tid & 3; \
          size_t srck_ = (size_t)(b * SS + k0_ + row_) * NQKV + colK + s2_ * 16; \
          uint32_t dstk_ = sb_ + FA_K + row_ * 144 + s2_ * 32; \
          CP_ASYNC16(dstk_, qkv + srck_); \
          CP_ASYNC16(dstk_ + 16, qkv + srck_ + 8); \
          size_t srcv_ = (size_t)(b * SS + k0_ + row_) * NQKV + colV + s2_ * 16; \
          uint32_t dstv_ = sb_ + FA_V + row_ * 144 + s2_ * 32; \
          CP_ASYNC16(dstv_, qkv + srcv_); \
          CP_ASYNC16(dstv_ + 16, qkv + srcv_ + 8); } \
        if (tid < 16) \
            CP_ASYNC16(sb_ + FA_MSK + tid * 16, tok + b * SS + k0_ + tid * 4); \
        CP_COMMIT(); \
    } while (0)

    FA_FILL(0);
    FA_FILL(1);

    uint32_t qf[4][4];
    CP_WAITG(2);
    __syncthreads();
    #pragma unroll
    for (int ks = 0; ks < 4; ks++) {
        uint32_t ad = (wid * 16 + lrow) * 144 + (ks * 16 + khalf * 8) * 2;
        LDM_X4(qf[ks][0], qf[ks][1], qf[ks][2], qf[ks][3], sQ + ad);
    }

    float m0 = -3.0e38f, m1 = -3.0e38f, l0 = 0.f, l1 = 0.f;
    float O[8][4];
    #pragma unroll
    for (int i = 0; i < 8; i++)
        #pragma unroll
        for (int j = 0; j < 4; j++) O[i][j] = 0.f;

    for (int kt = 0; kt < 16; kt++) {
        if (kt + 2 < 16) { FA_FILL(kt + 2); CP_WAITG(2); }
        else if (kt + 1 < 16) CP_WAITG(1);
        else CP_WAITG(0);
        __syncthreads();

        const uint32_t sb = base + FA_STG0 + (uint32_t)(kt & 3) * FA_STGSZ;
        const uint32_t sK = sb + FA_K, sV = sb + FA_V;
        const int* toki = (const int*)(smem_raw + FA_STG0 + (kt & 3) * FA_STGSZ + FA_MSK);

        float Sv[8][4];
        #pragma unroll
        for (int i = 0; i < 8; i++)
            #pragma unroll
            for (int j = 0; j < 4; j++) Sv[i][j] = 0.f;

        #pragma unroll
        for (int ks = 0; ks < 4; ks++) {
            #pragma unroll
            for (int ng = 0; ng < 4; ng++) {
                uint32_t bd = (ng * 16 + lrow) * 144 + (ks * 16 + khalf * 8) * 2;
                uint32_t bh_[4];
                LDM_X4(bh_[0], bh_[1], bh_[2], bh_[3], sK + bd);
                MMA_F16(Sv[2 * ng],     qf[ks], bh_[0], bh_[2]);
                MMA_F16(Sv[2 * ng + 1], qf[ks], bh_[1], bh_[3]);
            }
        }

        float mt0 = -3.0e38f, mt1 = -3.0e38f;
        #pragma unroll
        for (int nb = 0; nb < 8; nb++) {
            float mk0 = (toki[nb * 8 + cpos]     == 0) ? -1e9f : 0.f;
            float mk1 = (toki[nb * 8 + cpos + 1] == 0) ? -1e9f : 0.f;
            Sv[nb][0] = Sv[nb][0] * 0.125f + mk0;
            Sv[nb][1] = Sv[nb][1] * 0.125f + mk1;
            Sv[nb][2] = Sv[nb][2] * 0.125f + mk0;
            Sv[nb][3] = Sv[nb][3] * 0.125f + mk1;
            mt0 = fmaxf(mt0, fmaxf(Sv[nb][0], Sv[nb][1]));
            mt1 = fmaxf(mt1, fmaxf(Sv[nb][2], Sv[nb][3]));
        }
        mt0 = fmaxf(mt0, __shfl_xor_sync(0xffffffffu, mt0, 1));
        mt0 = fmaxf(mt0, __shfl_xor_sync(0xffffffffu, mt0, 2));
        mt1 = fmaxf(mt1, __shfl_xor_sync(0xffffffffu, mt1, 1));
        mt1 = fmaxf(mt1, __shfl_xor_sync(0xffffffffu, mt1, 2));

        float mn0 = fmaxf(m0, mt0), mn1 = fmaxf(m1, mt1);
        float al0 = __expf(m0 - mn0), al1 = __expf(m1 - mn1);
        float su0 = 0.f, su1 = 0.f;
        #pragma unroll
        for (int nb = 0; nb < 8; nb++) {
            Sv[nb][0] = __expf(Sv[nb][0] - mn0);
            Sv[nb][1] = __expf(Sv[nb][1] - mn0);
            Sv[nb][2] = __expf(Sv[nb][2] - mn1);
            Sv[nb][3] = __expf(Sv[nb][3] - mn1);
            su0 += Sv[nb][0] + Sv[nb][1];
            su1 += Sv[nb][2] + Sv[nb][3];
        }
        su0 += __shfl_xor_sync(0xffffffffu, su0, 1);
        su0 += __shfl_xor_sync(0xffffffffu, su0, 2);
        su1 += __shfl_xor_sync(0xffffffffu, su1, 1);
        su1 += __shfl_xor_sync(0xffffffffu, su1, 2);

        l0 = l0 * al0 + su0;
        l1 = l1 * al1 + su1;
        m0 = mn0; m1 = mn1;
        #pragma unroll
        for (int nf = 0; nf < 8; nf++) {
            O[nf][0] *= al0; O[nf][1] *= al0;
            O[nf][2] *= al1; O[nf][3] *= al1;
        }

        #pragma unroll
        for (int j = 0; j < 4; j++) {
            uint32_t pa[4];
            pa[0] = hpk2(Sv[2*j][0],   Sv[2*j][1]);
            pa[1] = hpk2(Sv[2*j][2],   Sv[2*j][3]);
            pa[2] = hpk2(Sv[2*j+1][0], Sv[2*j+1][1]);
            pa[3] = hpk2(Sv[2*j+1][2], Sv[2*j+1][3]);
            #pragma unroll
            for (int ng = 0; ng < 4; ng++) {
                uint32_t bd = sV + (j * 16 + lrow) * 144 + (ng * 16 + khalf * 8) * 2;
                uint32_t v0, v1, v2, v3;
                LDM_X4_T(v0, v1, v2, v3, bd);
                MMA_F16(O[2 * ng],     pa, v0, v1);
                MMA_F16(O[2 * ng + 1], pa, v2, v3);
            }
        }
    }
    #undef FA_FILL

    float i0 = 1.f / l0, i1 = 1.f / l1;
    const int rgl = b * SS + q0 + wid * 16 + (lane >> 2);
    #pragma unroll
    for (int nf = 0; nf < 8; nf++) {
        int col = h * 64 + nf * 8 + cpos;
        size_t o0 = (size_t)rgl * HDD + col;
        size_t o1 = (size_t)(rgl + 8) * HDD + col;
        *(uint32_t*)(ch + o0) = hpk2(O[nf][0] * i0, O[nf][1] * i0);
        *(uint32_t*)(ch + o1) = hpk2(O[nf][2] * i1, O[nf][3] * i1);
    }
}

// ==================== embed + add_ln (vectorized, single-pass LN) ====================
__global__ __launch_bounds__(256) void embed_kernel(
    const int* __restrict__ tok, const float* __restrict__ emb,
    float* __restrict__ x, __half* __restrict__ xh)
{
    int row = blockIdx.x;
    int s = row % SS;
    int t = tok[row];
    const float* e = emb + (size_t)t * DD;
    int d = threadIdx.x * 4;
    float4 ev = *(const float4*)&e[d];
    float pv[4];
    #pragma unroll
    for (int j = 0; j < 4; j++) {
        int dd = d + j;
        int i = dd >> 1;
        float freq = __expf(-((float)(2 * i) / (float)DD) * 9.210340371976184f);
        float a = (float)s * freq;
        pv[j] = (dd & 1) ? cosf(a) : sinf(a);
    }
    float4 v = make_float4(ev.x + pv[0], ev.y + pv[1], ev.z + pv[2], ev.w + pv[3]);
    size_t o = (size_t)row * DD + d;
    *(float4*)&x[o] = v;
    *(uint32_t*)&xh[o]     = hpk2(v.x, v.y);
    *(uint32_t*)&xh[o + 2] = hpk2(v.z, v.w);
}

// combined (sum, sumsq) block reduction: one barrier round
__device__ __forceinline__ float2 block_sum2(float a, float b, float2* sh) {
    #pragma unroll
    for (int o = 16; o > 0; o >>= 1) {
        a += __shfl_xor_sync(0xffffffffu, a, o);
        b += __shfl_xor_sync(0xffffffffu, b, o);
    }
    int w = threadIdx.x >> 5;
    if ((threadIdx.x & 31) == 0) sh[w] = make_float2(a, b);
    __syncthreads();
    float ta = (threadIdx.x < 8) ? sh[threadIdx.x].x : 0.0f;
    float tb = (threadIdx.x < 8) ? sh[threadIdx.x].y : 0.0f;
    #pragma unroll
    for (int o = 4; o > 0; o >>= 1) {
        ta += __shfl_xor_sync(0xffffffffu, ta, o);
        tb += __shfl_xor_sync(0xffffffffu, tb, o);
    }
    if (threadIdx.x == 0) sh[0] = make_float2(ta, tb);
    __syncthreads();
    return sh[0];
}

__global__ __launch_bounds__(256) void add_ln(
    const float* __restrict__ xin, const float* __restrict__ delta,
    const float* __restrict__ g, const float* __restrict__ bta,
    float* __restrict__ out, __half* __restrict__ oh)
{
    size_t row = blockIdx.x;
    const float* xr = xin   + row * DD;
    const float* dr = delta + row * DD;
    int tid = threadIdx.x;
    __shared__ float2 red[8];

    int c = tid * 4;
    float4 xv = *(const float4*)&xr[c];
    float4 dv = *(const float4*)&dr[c];
    float v[4] = { xv.x + dv.x, xv.y + dv.y, xv.z + dv.z, xv.w + dv.w };
    float s  = (v[0] + v[1]) + (v[2] + v[3]);
    float s2 = (v[0]*v[0] + v[1]*v[1]) + (v[2]*v[2] + v[3]*v[3]);
    float2 r = block_sum2(s, s2, red);
    float mu  = r.x * (1.0f / 1024.0f);
    float var = fmaxf(r.y * (1.0f / 1024.0f) - mu * mu, 0.0f);
    float inv = rsqrtf(var + 1e-5f);

    float4 gv = *(const float4*)&g[c];
    float4 bv = *(const float4*)&bta[c];
    float4 ov;
    ov.x = (v[0] - mu) * inv * gv.x + bv.x;
    ov.y = (v[1] - mu) * inv * gv.y + bv.y;
    ov.z = (v[2] - mu) * inv * gv.z + bv.z;
    ov.w = (v[3] - mu) * inv * gv.w + bv.w;
    size_t idx = row * DD + c;
    *(float4*)&out[idx] = ov;
    if (oh) {
        *(uint32_t*)&oh[idx]     = hpk2(ov.x, ov.y);
        *(uint32_t*)&oh[idx + 2] = hpk2(ov.z, ov.w);
    }
}

// ==================== host orchestration ====================
extern "C" void kernel_launch(void* const* d_in, const int* in_sizes, int n_in,
                              void* d_out, int out_size)
{
    (void)in_sizes; (void)n_in; (void)out_size;
    const int*   tok  = (const int*)  d_in[0];
    const float* emb  = (const float*)d_in[1];
    const float* Wq   = (const float*)d_in[2];
    const float* bq   = (const float*)d_in[3];
    const float* Wk   = (const float*)d_in[4];
    const float* bk   = (const float*)d_in[5];
    const float* Wv   = (const float*)d_in[6];
    const float* bv   = (const float*)d_in[7];
    const float* Wo   = (const float*)d_in[8];
    const float* bo   = (const float*)d_in[9];
    const float* ln1g = (const float*)d_in[10];
    const float* ln1b = (const float*)d_in[11];
    const float* W1   = (const float*)d_in[12];
    const float* W2   = (const float*)d_in[13];
    const float* ln2g = (const float*)d_in[14];
    const float* ln2b = (const float*)d_in[15];
    float* out = (float*)d_out;

    float *x, *tmp, *bqkv;
    __half *xh, *qkv, *ch, *fh, *wh;
    cudaGetSymbolAddress((void**)&x,     g_x);
    cudaGetSymbolAddress((void**)&tmp,   g_tmp);
    cudaGetSymbolAddress((void**)&xh,    g_xh);
    cudaGetSymbolAddress((void**)&qkv,   g_qkv);
    cudaGetSymbolAddress((void**)&ch,    g_ch);
    cudaGetSymbolAddress((void**)&fh,    g_fh);
    cudaGetSymbolAddress((void**)&wh,    g_wh);
    cudaGetSymbolAddress((void**)&bqkv,  g_bqkv);

    const int GSM128 = 3 * (128 * SPB + ARR_BB);   // 110592
    const int GSM64  = 3 * (64 * SPB + ARR_BB);    // 82944

    static int attr_done = 0;
    static cudaStream_t s2;
    static cudaEvent_t evFork, evPrep, evJoin;
    if (!attr_done) {
        cudaFuncSetAttribute(gemm_mma<128>, cudaFuncAttributeMaxDynamicSharedMemorySize, GSM128);
        cudaFuncSetAttribute(gemm_mma<64>,  cudaFuncAttributeMaxDynamicSharedMemorySize, GSM64);
        cudaFuncSetAttribute(flash_attn, cudaFuncAttributeMaxDynamicSharedMemorySize, FA_SMEM);
        cudaStreamCreateWithFlags(&s2, cudaStreamNonBlocking);
        cudaEventCreateWithFlags(&evFork, cudaEventDisableTiming);
        cudaEventCreateWithFlags(&evPrep, cudaEventDisableTiming);
        cudaEventCreateWithFlags(&evJoin, cudaEventDisableTiming);
        attr_done = 1;
    }

    cudaEventRecord(evFork, 0);
    cudaStreamWaitEvent(s2, evFork, 0);

    embed_kernel<<<MR, 256>>>(tok, emb, x, xh);

    biascat_kernel<<<LL * NQKV / 256, 256, 0, s2>>>(bq, bk, bv, bqkv);
    tsplit_qkv<<<dim3(HDD/64, DD/64, LL*3), 256, 0, s2>>>(Wq, Wk, Wv, wh + WQKV_OFF);
    cudaEventRecord(evPrep, s2);
    tsplit_b<<<dim3(DD/64, HDD/64, LL), 256, 0, s2>>>(Wo, wh + WOT_OFF, HDD, DD);
    tsplit_b<<<dim3(FF/64, DD/64, LL), 256, 0, s2>>>(W1, wh + W1T_OFF, DD, FF);
    tsplit_b<<<dim3(DD/64, FF/64, LL), 256, 0, s2>>>(W2, wh + W2T_OFF, FF, DD);
    cudaEventRecord(evJoin, s2);

    cudaStreamWaitEvent(0, evPrep, 0);

    dim3 gQKV(NQKV/128, MR/128);   // MT=128
    dim3 gWo(DD/128, MR/64);       // MT=64
    dim3 gF1(FF/128, MR/128);      // MT=128
    dim3 gF2(DD/128, MR/64);       // MT=64
    dim3 gFA(SS/128, BB*HH);

    for (int l = 0; l < LL; l++) {
        const __half* wqkv = wh + WQKV_OFF + (size_t)l * 3 * SZ_P;
        const __half* woh  = wh + WOT_OFF + (size_t)l * SZ_P;
        const __half* w1h  = wh + W1T_OFF + (size_t)l * SZ_F;
        const __half* w2h  = wh + W2T_OFF + (size_t)l * SZ_F;

        gemm_mma<128><<<gQKV, 256, GSM128>>>(xh, wqkv, bqkv + (size_t)l*NQKV,
                                             (float*)nullptr, qkv, DD, NQKV, 0);

        flash_attn<<<gFA, 256, FA_SMEM>>>(qkv, tok, ch);

        if (l == 0) cudaStreamWaitEvent(0, evJoin, 0);

        gemm_mma<64><<<gWo, 256, GSM64>>>(ch, woh, bo + (size_t)l*DD,
                                          tmp, (__half*)nullptr, HDD, DD, 0);
        add_ln<<<MR, 256>>>(x, tmp, ln1g + (size_t)l*DD, ln1b + (size_t)l*DD, x, xh);

        gemm_mma<128><<<gF1, 256, GSM128>>>(xh, w1h, (const float*)nullptr,
                                            (float*)nullptr, fh, DD, FF, 1);
        gemm_mma<64><<<gF2, 256, GSM64>>>(fh, w2h, (const float*)nullptr,
                                          tmp, (__half*)nullptr, FF, DD, 0);

        float* dst = (l == LL - 1) ? out : x;
        __half* dsth = (l == LL - 1) ? (__half*)nullptr : xh;
        add_ln<<<MR, 256>>>(x, tmp, ln2g + (size_t)l*DD, ln2b + (size_t)l*DD, dst, dsth);
    }
}